// round 8
// baseline (speedup 1.0000x reference)
#include <cuda_runtime.h>
#include <cuda_bf16.h>
#include <math.h>
#include <float.h>
#include <stdint.h>

#define BATCH 8
#define LSEQ 1024
#define DMODEL 768
#define D2V 1536
#define N2X 3072
#define NSTATE 16
#define ROWS (BATCH*LSEQ)
#define K3 (3*LSEQ)

// narrow kernel (128x128) for GEMM6
#define BM 128
#define BN 128
#define NSTAGES 3
#define NSTAGE_BYTES 65536u
#define NSMEM (NSTAGES*NSTAGE_BYTES)

// wide kernel (128x256)
#define WSTAGE 98304u
#define WOFF_AL 16384u
#define WOFF_BH 32768u
#define WOFF_BL 65536u
#define WSMEM (2u*WSTAGE)

// side kernel (128x32)
#define SSTAGE 40960u
#define SOFF_AL 16384u
#define SOFF_BH 32768u
#define SOFF_BL 36864u
#define SSMEM (3u*SSTAGE)

typedef __nv_bfloat16 bf16;

// ------------------------- device scratch -------------------------
__device__ float g_x   [ROWS*DMODEL];
__device__ float g_xres[(size_t)ROWS*D2V];
__device__ float g_bc  [ROWS*32];
__device__ float g_rowsum[ROWS];
__device__ float g_rowsq [ROWS];
__device__ float g_mu  [BATCH];
__device__ float g_rsig[BATCH];
__device__ float g_s   [ROWS];
__device__ float g_b15 [N2X];
__device__ float g_b23 [32];

__device__ bf16 g_xnP_h [ROWS*DMODEL], g_xnP_l [ROWS*DMODEL];
__device__ bf16 g_xcaP_h[ROWS*D2V],    g_xcaP_l[ROWS*D2V];
__device__ bf16 g_xcoP_h[ROWS*D2V],    g_xcoP_l[ROWS*D2V];
__device__ bf16 g_prP_h [ROWS*D2V],    g_prP_l [ROWS*D2V];
__device__ bf16 g_W15_h [DMODEL*N2X],  g_W15_l [DMODEL*N2X];
__device__ bf16 g_WclS_h[D2V*D2V],     g_WclS_l[D2V*D2V];
__device__ bf16 g_f1_h  [D2V*D2V],     g_f1_l  [D2V*D2V];
__device__ bf16 g_f23_h [D2V*32],      g_f23_l [D2V*32];
__device__ bf16 g_WoS_h [D2V*DMODEL],  g_WoS_l [D2V*DMODEL];
__device__ bf16 g_cA_h  [LSEQ*K3],     g_cA_l  [LSEQ*K3];
// zero-initialized; boundary entries (k=0,t'=0 and k=2,t'=1535) are never written and stay 0
__device__ bf16 g_cB_h  [(size_t)BATCH*K3*D2V];
__device__ bf16 g_cB_l  [(size_t)BATCH*K3*D2V];

// ------------------------- helpers -------------------------
__device__ __forceinline__ float siluf(float v){ return v / (1.f + expf(-v)); }
__device__ __forceinline__ float softplusf(float v){ return (v > 20.f) ? v : log1pf(expf(v)); }

__device__ __forceinline__ uint32_t smem_u32(const void* p){
    uint32_t a;
    asm("{ .reg .u64 t; cvta.to.shared.u64 t, %1; cvt.u32.u64 %0, t; }" : "=r"(a) : "l"(p));
    return a;
}
__device__ __forceinline__ void cpa16(uint32_t dst, const void* src){
    asm volatile("cp.async.cg.shared.global [%0], [%1], 16;" :: "r"(dst), "l"(src) : "memory");
}
#define CP_COMMIT() asm volatile("cp.async.commit_group;" ::: "memory")
#define CP_WAIT(n)  asm volatile("cp.async.wait_group %0;" :: "n"(n) : "memory")

__device__ __forceinline__ void ldsm4(uint32_t addr, uint32_t* r){
    asm volatile("ldmatrix.sync.aligned.m8n8.x4.shared.b16 {%0,%1,%2,%3}, [%4];"
        : "=r"(r[0]), "=r"(r[1]), "=r"(r[2]), "=r"(r[3]) : "r"(addr));
}
__device__ __forceinline__ void ldsm4t(uint32_t addr, uint32_t* r0, uint32_t* r1){
    asm volatile("ldmatrix.sync.aligned.m8n8.x4.trans.shared.b16 {%0,%1,%2,%3}, [%4];"
        : "=r"(r0[0]), "=r"(r0[1]), "=r"(r1[0]), "=r"(r1[1]) : "r"(addr));
}
__device__ __forceinline__ void mma16816(float* d, const uint32_t* a, const uint32_t* b){
    asm volatile("mma.sync.aligned.m16n8k16.row.col.f32.bf16.bf16.f32 "
        "{%0,%1,%2,%3}, {%4,%5,%6,%7}, {%8,%9}, {%0,%1,%2,%3};"
        : "+f"(d[0]), "+f"(d[1]), "+f"(d[2]), "+f"(d[3])
        : "r"(a[0]), "r"(a[1]), "r"(a[2]), "r"(a[3]), "r"(b[0]), "r"(b[1]));
}
__device__ __forceinline__ void splitf(float v, bf16& h, bf16& l){
    h = __float2bfloat16(v);
    l = __float2bfloat16(v - __bfloat162float(h));
}

// ------------------------- WIDE HMMA GEMM 128x256 -------------------------
// EPI: 1 = conv (silu + biasM, split out)
//      2 = biasN, split out (GEMM3)
//      4 = GEMM1+5: cols<1536 -> scatter split into cB (conv operand); cols>=1536 -> fp32 xres
//      5 = GEMM4: delta=softplus -> prod epilogue, split out
template<int EPI>
__global__ void __launch_bounds__(256, 1) k_tcW(
    const bf16* __restrict__ Ah, const bf16* __restrict__ Al,
    const bf16* __restrict__ Bh, const bf16* __restrict__ Bl,
    const float* __restrict__ biasN, const float* __restrict__ biasM,
    bf16* __restrict__ Ch, bf16* __restrict__ Cl,
    const bf16* __restrict__ Xh, const bf16* __restrict__ Xl,
    float* __restrict__ Xf, const float* __restrict__ Sv,
    int K, int N, long sA, long sB, long sC)
{
    extern __shared__ char smem[];
    const int tid  = threadIdx.x;
    const int wid  = tid >> 5, lane = tid & 31;
    const int wm   = wid & 1,  wn = wid >> 1;
    const int row0 = blockIdx.y * 128;
    const int col0 = blockIdx.x * 256;
    Ah += (size_t)blockIdx.z * sA;  Al += (size_t)blockIdx.z * sA;
    Bh += (size_t)blockIdx.z * sB;  Bl += (size_t)blockIdx.z * sB;
    if (Ch){ Ch += (size_t)blockIdx.z * sC; Cl += (size_t)blockIdx.z * sC; }
    const int NK = K >> 6;
    const uint32_t sbase = smem_u32(smem);

    float acc[4][8][4];
    #pragma unroll
    for (int mi = 0; mi < 4; mi++)
        #pragma unroll
        for (int nj = 0; nj < 8; nj++)
            #pragma unroll
            for (int q = 0; q < 4; q++) acc[mi][nj][q] = 0.f;

    auto fill = [&](int kc, int s){
        uint32_t st = sbase + (uint32_t)s * WSTAGE;
        const bf16* ap[2] = { Ah, Al };
        #pragma unroll
        for (int arr = 0; arr < 2; arr++){
            uint32_t base = st + arr * WOFF_AL;
            #pragma unroll
            for (int it = 0; it < 4; it++){
                int id = tid + it * 256;
                int r = id >> 3, u = id & 7;
                cpa16(base + r * 128 + (((uint32_t)(u ^ (r & 7))) << 4),
                      ap[arr] + (size_t)(row0 + r) * K + kc * 64 + u * 8);
            }
        }
        const bf16* bp[2] = { Bh, Bl };
        #pragma unroll
        for (int arr = 0; arr < 2; arr++){
            uint32_t base = st + WOFF_BH + arr * (WOFF_BL - WOFF_BH);
            #pragma unroll
            for (int it = 0; it < 8; it++){
                int id = tid + it * 256;
                int k = id >> 5, u = id & 31;
                cpa16(base + k * 512 + (((uint32_t)(u ^ (k & 7))) << 4),
                      bp[arr] + (size_t)(kc * 64 + k) * N + col0 + u * 8);
            }
        }
        CP_COMMIT();
    };

    fill(0, 0);
    fill(1, 1);

    for (int kc = 0; kc < NK; kc++){
        int s = kc & 1;
        CP_WAIT(1);
        __syncthreads();

        uint32_t aAh = sbase + (uint32_t)s * WSTAGE;
        uint32_t aAl = aAh + WOFF_AL;
        uint32_t aBh = aAh + WOFF_BH;
        uint32_t aBl = aAh + WOFF_BL;

        #pragma unroll
        for (int ks = 0; ks < 4; ks++){
            uint32_t ah[4][4], al[4][4];
            const int au = 2 * ks + (lane >> 4);
            #pragma unroll
            for (int mi = 0; mi < 4; mi++){
                int r = wm * 64 + mi * 16 + (lane & 15);
                uint32_t off = r * 128 + (((uint32_t)(au ^ (r & 7))) << 4);
                ldsm4(aAh + off, ah[mi]);
                ldsm4(aAl + off, al[mi]);
            }
            const int bk = ks * 16 + (lane & 15);
            #pragma unroll
            for (int p = 0; p < 4; p++){
                int u = wn * 8 + p * 2 + (lane >> 4);
                uint32_t off = bk * 512 + (((uint32_t)(u ^ (bk & 7))) << 4);
                uint32_t b0[2], b1[2];
                ldsm4t(aBh + off, b0, b1);
                #pragma unroll
                for (int mi = 0; mi < 4; mi++){
                    mma16816(acc[mi][2*p],   ah[mi], b0);
                    mma16816(acc[mi][2*p+1], ah[mi], b1);
                }
                #pragma unroll
                for (int mi = 0; mi < 4; mi++){
                    mma16816(acc[mi][2*p],   al[mi], b0);
                    mma16816(acc[mi][2*p+1], al[mi], b1);
                }
            }
            #pragma unroll
            for (int p = 0; p < 4; p++){
                int u = wn * 8 + p * 2 + (lane >> 4);
                uint32_t off = bk * 512 + (((uint32_t)(u ^ (bk & 7))) << 4);
                uint32_t b0[2], b1[2];
                ldsm4t(aBl + off, b0, b1);
                #pragma unroll
                for (int mi = 0; mi < 4; mi++){
                    mma16816(acc[mi][2*p],   ah[mi], b0);
                    mma16816(acc[mi][2*p+1], ah[mi], b1);
                }
            }
        }

        __syncthreads();
        if (kc + 2 < NK) fill(kc + 2, s);
        else CP_COMMIT();
    }

    CP_WAIT(0);
    __syncthreads();

    // ---- epilogue: acc -> smem (260-pitch) -> global
    float* sf = (float*)smem;
    {
        const int rlo = lane >> 2;
        const int ncl = (lane & 3) * 2;
        #pragma unroll
        for (int mi = 0; mi < 4; mi++)
            #pragma unroll
            for (int nj = 0; nj < 8; nj++){
                int m = wm * 64 + mi * 16 + rlo;
                int n = wn * 64 + nj * 8 + ncl;
                *(float2*)&sf[(size_t)m * 260 + n]       = make_float2(acc[mi][nj][0], acc[mi][nj][1]);
                *(float2*)&sf[(size_t)(m + 8) * 260 + n] = make_float2(acc[mi][nj][2], acc[mi][nj][3]);
            }
    }
    __syncthreads();

    for (int i = tid; i < 128 * 64; i += 256){
        int r = i >> 6, c = (i & 63) * 4;
        int row = row0 + r;
        int col = col0 + c;
        float4 v4 = *(float4*)&sf[(size_t)r * 260 + c];
        float vv[4] = { v4.x, v4.y, v4.z, v4.w };

        if (EPI == 1){
            float bm = __ldg(biasM + row);
            #pragma unroll
            for (int j = 0; j < 4; j++) vv[j] = siluf(vv[j] + bm);
            bf16 hh[4], ll[4];
            #pragma unroll
            for (int j = 0; j < 4; j++) splitf(vv[j], hh[j], ll[j]);
            size_t o = (size_t)row * N + col;
            *(uint2*)(Ch + o) = *(uint2*)hh;
            *(uint2*)(Cl + o) = *(uint2*)ll;
        }
        else if (EPI == 2){
            #pragma unroll
            for (int j = 0; j < 4; j++) vv[j] += __ldg(biasN + col + j);
            bf16 hh[4], ll[4];
            #pragma unroll
            for (int j = 0; j < 4; j++) splitf(vv[j], hh[j], ll[j]);
            size_t o = (size_t)row * N + col;
            *(uint2*)(Ch + o) = *(uint2*)hh;
            *(uint2*)(Cl + o) = *(uint2*)ll;
        }
        else if (EPI == 4){
            #pragma unroll
            for (int j = 0; j < 4; j++) vv[j] += __ldg(biasN + col + j);
            if (col < D2V){
                // scatter into conv B operand: cB[b][k*1024+i][t+1-k] = xp[b][i][t]
                int b = row >> 10, irow = row & 1023;
                bf16 hh[4], ll[4];
                #pragma unroll
                for (int j = 0; j < 4; j++) splitf(vv[j], hh[j], ll[j]);
                #pragma unroll
                for (int k = 0; k < 3; k++){
                    size_t base = ((size_t)b * K3 + k * 1024 + irow) * (size_t)D2V;
                    #pragma unroll
                    for (int j = 0; j < 4; j++){
                        int tp = col + j + 1 - k;
                        if (tp >= 0 && tp < D2V){
                            Ch[base + tp] = hh[j];
                            Cl[base + tp] = ll[j];
                        }
                    }
                }
            } else {
                *(float4*)(Xf + (size_t)row * D2V + (col - D2V)) = make_float4(vv[0], vv[1], vv[2], vv[3]);
            }
        }
        else if (EPI == 5){
            float sv = __ldg(Sv + row);
            size_t o = (size_t)row * N + col;
            uint2 xh2 = __ldg((const uint2*)(Xh + o));
            uint2 xl2 = __ldg((const uint2*)(Xl + o));
            float4 xr4 = __ldg((const float4*)(Xf + o));
            const bf16* xhp = (const bf16*)&xh2;
            const bf16* xlp = (const bf16*)&xl2;
            const float* xrp = (const float*)&xr4;
            bf16 hh[4], ll[4];
            #pragma unroll
            for (int j = 0; j < 4; j++){
                float delta = softplusf(vv[j] + __ldg(biasN + col + j));
                float xco = __bfloat162float(xhp[j]) + __bfloat162float(xlp[j]);
                float pr = siluf(xco * delta * sv) * siluf(xrp[j]);
                splitf(pr, hh[j], ll[j]);
            }
            *(uint2*)(Ch + o) = *(uint2*)hh;
            *(uint2*)(Cl + o) = *(uint2*)ll;
        }
    }
}

// ------------------------- NARROW HMMA GEMM 128x128 (GEMM6) ----
__global__ void __launch_bounds__(256, 1) k_tcN(
    const bf16* __restrict__ Ah, const bf16* __restrict__ Al,
    const bf16* __restrict__ Bh, const bf16* __restrict__ Bl,
    const float* __restrict__ biasN,
    float* __restrict__ C, int K, int N)
{
    extern __shared__ char smem[];
    const int tid  = threadIdx.x;
    const int wid  = tid >> 5, lane = tid & 31;
    const int wm   = wid & 3,  wn = wid >> 2;
    const int row0 = blockIdx.y * BM;
    const int col0 = blockIdx.x * BN;
    const int NK = K >> 6;
    const uint32_t sbase = smem_u32(smem);

    float acc[2][8][4];
    #pragma unroll
    for (int mi = 0; mi < 2; mi++)
        #pragma unroll
        for (int nj = 0; nj < 8; nj++)
            #pragma unroll
            for (int q = 0; q < 4; q++) acc[mi][nj][q] = 0.f;

    auto fill = [&](int kc, int s){
        uint32_t st = sbase + (uint32_t)s * NSTAGE_BYTES;
        const bf16* ap[2] = { Ah, Al };
        #pragma unroll
        for (int arr = 0; arr < 2; arr++){
            uint32_t base = st + arr * 16384u;
            #pragma unroll
            for (int it = 0; it < 4; it++){
                int id = tid + it * 256;
                int r = id >> 3, u = id & 7;
                cpa16(base + r * 128 + (((uint32_t)(u ^ (r & 7))) << 4),
                      ap[arr] + (size_t)(row0 + r) * K + kc * 64 + u * 8);
            }
        }
        const bf16* bp[2] = { Bh, Bl };
        #pragma unroll
        for (int arr = 0; arr < 2; arr++){
            uint32_t base = st + 32768u + arr * 16384u;
            #pragma unroll
            for (int it = 0; it < 4; it++){
                int id = tid + it * 256;
                int k = id >> 4, u = id & 15;
                cpa16(base + k * 256 + (((uint32_t)(u ^ (k & 7))) << 4),
                      bp[arr] + (size_t)(kc * 64 + k) * N + col0 + u * 8);
            }
        }
        CP_COMMIT();
    };

    fill(0, 0);
    if (NK > 1) fill(1, 1); else CP_COMMIT();

    for (int kc = 0; kc < NK; kc++){
        int s = kc % NSTAGES;
        CP_WAIT(1);
        __syncthreads();

        uint32_t aAh = sbase + (uint32_t)s * NSTAGE_BYTES;
        uint32_t aAl = aAh + 16384u;
        uint32_t aBh = aAh + 32768u;
        uint32_t aBl = aAh + 49152u;

        #pragma unroll
        for (int ks = 0; ks < 4; ks++){
            uint32_t ah[2][4], al[2][4], bb[8][2];
            const int arow = wm * 32 + (lane & 15);
            const int au   = 2 * ks + (lane >> 4);
            #pragma unroll
            for (int mi = 0; mi < 2; mi++){
                int r = arow + mi * 16;
                uint32_t off = r * 128 + (((uint32_t)(au ^ (r & 7))) << 4);
                ldsm4(aAh + off, ah[mi]);
                ldsm4(aAl + off, al[mi]);
            }
            const int bk = ks * 16 + (lane & 15);
            #pragma unroll
            for (int p = 0; p < 4; p++){
                int u = wn * 8 + p * 2 + (lane >> 4);
                uint32_t off = bk * 256 + (((uint32_t)(u ^ (bk & 7))) << 4);
                ldsm4t(aBh + off, bb[2*p], bb[2*p+1]);
            }
            #pragma unroll
            for (int mi = 0; mi < 2; mi++)
                #pragma unroll
                for (int nj = 0; nj < 8; nj++)
                    mma16816(acc[mi][nj], ah[mi], bb[nj]);
            #pragma unroll
            for (int mi = 0; mi < 2; mi++)
                #pragma unroll
                for (int nj = 0; nj < 8; nj++)
                    mma16816(acc[mi][nj], al[mi], bb[nj]);
            #pragma unroll
            for (int p = 0; p < 4; p++){
                int u = wn * 8 + p * 2 + (lane >> 4);
                uint32_t off = bk * 256 + (((uint32_t)(u ^ (bk & 7))) << 4);
                ldsm4t(aBl + off, bb[2*p], bb[2*p+1]);
            }
            #pragma unroll
            for (int mi = 0; mi < 2; mi++)
                #pragma unroll
                for (int nj = 0; nj < 8; nj++)
                    mma16816(acc[mi][nj], ah[mi], bb[nj]);
        }

        if (kc + 2 < NK) fill(kc + 2, (kc + 2) % NSTAGES);
        else CP_COMMIT();
    }

    __syncthreads();
    float* sf = (float*)smem;
    {
        const int mrow = wm * 32 + (lane >> 2);
        const int ncol = wn * 64 + (lane & 3) * 2;
        #pragma unroll
        for (int mi = 0; mi < 2; mi++)
            #pragma unroll
            for (int nj = 0; nj < 8; nj++){
                int m = mrow + mi * 16, n = ncol + nj * 8;
                *(float2*)&sf[(size_t)m * 132 + n]       = make_float2(acc[mi][nj][0], acc[mi][nj][1]);
                *(float2*)&sf[(size_t)(m + 8) * 132 + n] = make_float2(acc[mi][nj][2], acc[mi][nj][3]);
            }
    }
    __syncthreads();

    for (int i = tid; i < BM * (BN / 4); i += 256){
        int r = i >> 5, c = (i & 31) * 4;
        float4 v = *(float4*)&sf[(size_t)r * 132 + c];
        float vv[4] = { v.x, v.y, v.z, v.w };
        #pragma unroll
        for (int j = 0; j < 4; j++)
            vv[j] += __ldg(biasN + col0 + c + j);
        *(float4*)(C + (size_t)(row0 + r) * N + col0 + c) = make_float4(vv[0], vv[1], vv[2], vv[3]);
    }
}

// ------------------------- SIDE GEMM 128x32 (Bm|Cm) -------------------------
__global__ void __launch_bounds__(256, 1) k_tcS(
    const bf16* __restrict__ Ah, const bf16* __restrict__ Al,
    const bf16* __restrict__ Bh, const bf16* __restrict__ Bl,
    const float* __restrict__ biasN, float* __restrict__ C, int K)
{
    extern __shared__ char smem[];
    const int tid = threadIdx.x;
    const int wid = tid >> 5, lane = tid & 31;
    const int row0 = blockIdx.y * 128;
    const int NK = K >> 6;
    const uint32_t sbase = smem_u32(smem);

    float acc[4][4];
    #pragma unroll
    for (int nj = 0; nj < 4; nj++)
        #pragma unroll
        for (int q = 0; q < 4; q++) acc[nj][q] = 0.f;

    auto fill = [&](int kc, int s){
        uint32_t st = sbase + (uint32_t)s * SSTAGE;
        const bf16* ap[2] = { Ah, Al };
        #pragma unroll
        for (int arr = 0; arr < 2; arr++){
            uint32_t base = st + arr * SOFF_AL;
            #pragma unroll
            for (int it = 0; it < 4; it++){
                int id = tid + it * 256;
                int r = id >> 3, u = id & 7;
                cpa16(base + r * 128 + (((uint32_t)(u ^ (r & 7))) << 4),
                      ap[arr] + (size_t)(row0 + r) * K + kc * 64 + u * 8);
            }
        }
        const bf16* bp[2] = { Bh, Bl };
        #pragma unroll
        for (int arr = 0; arr < 2; arr++){
            uint32_t base = st + SOFF_BH + arr * (SOFF_BL - SOFF_BH);
            int k = tid >> 2, u = tid & 3;
            cpa16(base + k * 64 + (((uint32_t)(u ^ (k & 3))) << 4),
                  bp[arr] + (size_t)(kc * 64 + k) * 32 + u * 8);
        }
        CP_COMMIT();
    };

    fill(0, 0);
    fill(1, 1);

    for (int kc = 0; kc < NK; kc++){
        int s = kc % 3;
        CP_WAIT(1);
        __syncthreads();

        uint32_t aAh = sbase + (uint32_t)s * SSTAGE;
        uint32_t aAl = aAh + SOFF_AL;
        uint32_t aBh = aAh + SOFF_BH;
        uint32_t aBl = aAh + SOFF_BL;

        #pragma unroll
        for (int ks = 0; ks < 4; ks++){
            uint32_t ah[4], al[4], bh[4][2], bl[4][2];
            const int r = wid * 16 + (lane & 15);
            const int au = 2 * ks + (lane >> 4);
            uint32_t offA = r * 128 + (((uint32_t)(au ^ (r & 7))) << 4);
            ldsm4(aAh + offA, ah);
            ldsm4(aAl + offA, al);
            const int bk = ks * 16 + (lane & 15);
            #pragma unroll
            for (int p = 0; p < 2; p++){
                int u = p * 2 + (lane >> 4);
                uint32_t off = bk * 64 + (((uint32_t)(u ^ (bk & 3))) << 4);
                ldsm4t(aBh + off, bh[2*p], bh[2*p+1]);
                ldsm4t(aBl + off, bl[2*p], bl[2*p+1]);
            }
            #pragma unroll
            for (int nj = 0; nj < 4; nj++){
                mma16816(acc[nj], ah, bh[nj]);
                mma16816(acc[nj], al, bh[nj]);
                mma16816(acc[nj], ah, bl[nj]);
            }
        }

        __syncthreads();
        if (kc + 2 < NK) fill(kc + 2, (kc + 2) % 3);
        else CP_COMMIT();
    }

    // direct epilogue (no smem staging; N=32)
    {
        int mrow = wid * 16 + (lane >> 2);
        int ncol = (lane & 3) * 2;
        #pragma unroll
        for (int nj = 0; nj < 4; nj++){
            int n = nj * 8 + ncol;
            float b0 = __ldg(biasN + n), b1 = __ldg(biasN + n + 1);
            *(float2*)&C[(size_t)(row0 + mrow) * 32 + n]     = make_float2(acc[nj][0] + b0, acc[nj][1] + b1);
            *(float2*)&C[(size_t)(row0 + mrow + 8) * 32 + n] = make_float2(acc[nj][2] + b0, acc[nj][3] + b1);
        }
    }
}

// ------------------------- prep (all weight packs, one launch) -------------------------
__device__ __forceinline__ void wsplit_job(int lb, int tid, const float* W,
                                           bf16* Wh, bf16* Wl, int Nsrc, int Ndst, int off)
{
    size_t i4 = (size_t)lb * 256 + tid;
    int nq = Nsrc / 4;
    int k  = (int)(i4 / nq);
    int c  = (int)(i4 % nq) * 4;
    float4 v = *(const float4*)(W + (size_t)k * Nsrc + c);
    bf16 hh[4], ll[4];
    splitf(v.x, hh[0], ll[0]); splitf(v.y, hh[1], ll[1]);
    splitf(v.z, hh[2], ll[2]); splitf(v.w, hh[3], ll[3]);
    size_t o = (size_t)k * Ndst + off + c;
    *(uint2*)(Wh + o) = *(uint2*)hh;
    *(uint2*)(Wl + o) = *(uint2*)ll;
}

__global__ void k_prep(const float* __restrict__ W_in, const float* __restrict__ W_D,
                       const float* __restrict__ W_cl, const float* __restrict__ fc1_w,
                       const float* __restrict__ W_out,
                       const float* __restrict__ fc2_w, const float* __restrict__ fc3_w,
                       const float* __restrict__ conv_w,
                       const float* __restrict__ b_in, const float* __restrict__ b_D,
                       const float* __restrict__ fc2_b, const float* __restrict__ fc3_b)
{
    int bid = blockIdx.x;
    int tid = threadIdx.x;
    if (bid < 1152){ wsplit_job(bid, tid, W_in, g_W15_h, g_W15_l, D2V, N2X, 0); return; }
    bid -= 1152;
    if (bid < 1152){ wsplit_job(bid, tid, W_D, g_W15_h, g_W15_l, D2V, N2X, D2V); return; }
    bid -= 1152;
    if (bid < 2304){ wsplit_job(bid, tid, W_cl, g_WclS_h, g_WclS_l, D2V, D2V, 0); return; }
    bid -= 2304;
    if (bid < 2304){ wsplit_job(bid, tid, fc1_w, g_f1_h, g_f1_l, D2V, D2V, 0); return; }
    bid -= 2304;
    if (bid < 1152){ wsplit_job(bid, tid, W_out, g_WoS_h, g_WoS_l, DMODEL, DMODEL, 0); return; }
    bid -= 1152;
    if (bid < 24){ wsplit_job(bid, tid, fc2_w, g_f23_h, g_f23_l, NSTATE, 32, 0); return; }
    bid -= 24;
    if (bid < 24){ wsplit_job(bid, tid, fc3_w, g_f23_h, g_f23_l, NSTATE, 32, NSTATE); return; }
    bid -= 24;
    if (bid < 4096){
        int o = bid >> 2;
        int i = (bid & 3) * 256 + tid;
        #pragma unroll
        for (int k = 0; k < 3; k++){
            float v = conv_w[(size_t)o * K3 + 3 * i + k];
            bf16 h, l; splitf(v, h, l);
            size_t off = (size_t)o * K3 + k * 1024 + i;
            g_cA_h[off] = h; g_cA_l[off] = l;
        }
        return;
    }
    bid -= 4096;
    if (bid < 12){
        int i = bid * 256 + tid;
        g_b15[i] = (i < D2V) ? b_in[i] : b_D[i - D2V];
        return;
    }
    bid -= 12;
    if (tid < 32) g_b23[tid] = (tid < NSTATE) ? fc2_b[tid] : fc3_b[tid - NSTATE];
}

// ------------------------- aux kernels -------------------------
__global__ void k_embed(const int* __restrict__ ids, const float* __restrict__ emb)
{
    int row = blockIdx.x;
    int id  = ids[row];
    const float* src = emb + (size_t)id * DMODEL;
    float s = 0.f, ss = 0.f;
    for (int d = threadIdx.x; d < DMODEL; d += blockDim.x){
        float v = __ldg(src + d);
        g_x[(size_t)row * DMODEL + d] = v;
        s += v; ss += v * v;
    }
    __shared__ float sh[64];
    int lane = threadIdx.x & 31, w = threadIdx.x >> 5;
    #pragma unroll
    for (int o = 16; o; o >>= 1){
        s  += __shfl_down_sync(0xffffffffu, s,  o);
        ss += __shfl_down_sync(0xffffffffu, ss, o);
    }
    if (!lane){ sh[w] = s; sh[32 + w] = ss; }
    __syncthreads();
    if (threadIdx.x == 0){
        float S = 0.f, SS = 0.f;
        int nw = blockDim.x >> 5;
        for (int i = 0; i < nw; i++){ S += sh[i]; SS += sh[32 + i]; }
        g_rowsum[row] = S; g_rowsq[row] = SS;
    }
}

__global__ void k_samplestats()
{
    int b = blockIdx.x;
    float s = 0.f, ss = 0.f;
    for (int r = threadIdx.x; r < LSEQ; r += blockDim.x){
        s += g_rowsum[b * LSEQ + r]; ss += g_rowsq[b * LSEQ + r];
    }
    __shared__ float sh[64];
    int lane = threadIdx.x & 31, w = threadIdx.x >> 5;
    #pragma unroll
    for (int o = 16; o; o >>= 1){
        s  += __shfl_down_sync(0xffffffffu, s,  o);
        ss += __shfl_down_sync(0xffffffffu, ss, o);
    }
    if (!lane){ sh[w] = s; sh[32 + w] = ss; }
    __syncthreads();
    if (threadIdx.x == 0){
        float S = 0.f, SS = 0.f;
        int nw = blockDim.x >> 5;
        for (int i = 0; i < nw; i++){ S += sh[i]; SS += sh[32 + i]; }
        float inv = 1.f / ((float)LSEQ * (float)DMODEL);
        float mu  = S * inv;
        float var = SS * inv - mu * mu;
        g_mu[b]   = mu;
        g_rsig[b] = rsqrtf(var + 1e-5f);
    }
}

__global__ void k_norm(const float* __restrict__ rms_w)
{
    int row = blockIdx.x;
    int b = row >> 10;
    float mu = g_mu[b], rs = g_rsig[b];
    float msq = rs * rs * (g_rowsq[row] - 2.f * mu * g_rowsum[row] + (float)DMODEL * mu * mu) / (float)DMODEL;
    float a = rs * rsqrtf(msq + 1e-5f);
    const float* xr = g_x + (size_t)row * DMODEL;
    for (int d = threadIdx.x; d < DMODEL; d += blockDim.x){
        float v = (xr[d] - mu) * a * rms_w[d];
        bf16 h, l; splitf(v, h, l);
        g_xnP_h[(size_t)row * DMODEL + d] = h;
        g_xnP_l[(size_t)row * DMODEL + d] = l;
    }
}

__global__ void k_s()
{
    int row = blockIdx.x;
    int lane = threadIdx.x;
    float p = 0.f;
    if (lane < NSTATE){
        float bm = g_bc[(size_t)row * 32 + lane];
        float cm = g_bc[(size_t)row * 32 + NSTATE + lane];
        p = bm * cm;
    }
    #pragma unroll
    for (int o = 8; o; o >>= 1) p += __shfl_xor_sync(0xffffffffu, p, o);
    if (lane == 0) g_s[row] = p;
}

__global__ void k_maxpool(const float* __restrict__ out, float* __restrict__ pooled)
{
    int b = blockIdx.y;
    int d = blockIdx.x * blockDim.x + threadIdx.x;
    if (d >= DMODEL) return;
    const float* p = out + (size_t)b * LSEQ * DMODEL + d;
    float m = -FLT_MAX;
    for (int l = 0; l < LSEQ; l++) m = fmaxf(m, p[(size_t)l * DMODEL]);
    pooled[b * DMODEL + d] = m;
}

// ------------------------- launch -------------------------
extern "C" void kernel_launch(void* const* d_in, const int* in_sizes, int n_in,
                              void* d_out, int out_size)
{
    const int*   ids    = (const int*)  d_in[0];
    const float* emb    = (const float*)d_in[1];
    const float* rms_w  = (const float*)d_in[2];
    const float* W_in   = (const float*)d_in[3];
    const float* b_in   = (const float*)d_in[4];
    const float* conv_w = (const float*)d_in[5];
    const float* conv_b = (const float*)d_in[6];
    const float* W_cl   = (const float*)d_in[7];
    const float* b_cl   = (const float*)d_in[8];
    const float* fc1_w  = (const float*)d_in[9];
    const float* fc1_b  = (const float*)d_in[10];
    const float* fc2_w  = (const float*)d_in[11];
    const float* fc2_b  = (const float*)d_in[12];
    const float* fc3_w  = (const float*)d_in[13];
    const float* fc3_b  = (const float*)d_in[14];
    const float* W_D    = (const float*)d_in[16];
    const float* b_D    = (const float*)d_in[17];
    const float* W_out  = (const float*)d_in[18];
    const float* b_out  = (const float*)d_in[19];
    float* out = (float*)d_out;

    cudaFuncSetAttribute(k_tcW<1>, cudaFuncAttributeMaxDynamicSharedMemorySize, WSMEM);
    cudaFuncSetAttribute(k_tcW<2>, cudaFuncAttributeMaxDynamicSharedMemorySize, WSMEM);
    cudaFuncSetAttribute(k_tcW<4>, cudaFuncAttributeMaxDynamicSharedMemorySize, WSMEM);
    cudaFuncSetAttribute(k_tcW<5>, cudaFuncAttributeMaxDynamicSharedMemorySize, WSMEM);
    cudaFuncSetAttribute(k_tcN,    cudaFuncAttributeMaxDynamicSharedMemorySize, NSMEM);
    cudaFuncSetAttribute(k_tcS,    cudaFuncAttributeMaxDynamicSharedMemorySize, SSMEM);

    bf16 *xnh, *xnl, *xcah, *xcal, *xcoh, *xcol, *prh, *prl;
    bf16 *w15h, *w15l, *wclh, *wcll, *f1h, *f1l, *f23h, *f23l, *woh, *wol;
    bf16 *cah, *cal, *cbh, *cbl;
    float *pxres, *pbc, *pb15, *pb23, *ps;
    cudaGetSymbolAddress((void**)&xnh,  g_xnP_h);  cudaGetSymbolAddress((void**)&xnl,  g_xnP_l);
    cudaGetSymbolAddress((void**)&xcah, g_xcaP_h); cudaGetSymbolAddress((void**)&xcal, g_xcaP_l);
    cudaGetSymbolAddress((void**)&xcoh, g_xcoP_h); cudaGetSymbolAddress((void**)&xcol, g_xcoP_l);
    cudaGetSymbolAddress((void**)&prh,  g_prP_h);  cudaGetSymbolAddress((void**)&prl,  g_prP_l);
    cudaGetSymbolAddress((void**)&w15h, g_W15_h);  cudaGetSymbolAddress((void**)&w15l, g_W15_l);
    cudaGetSymbolAddress((void**)&wclh, g_WclS_h); cudaGetSymbolAddress((void**)&wcll, g_WclS_l);
    cudaGetSymbolAddress((void**)&f1h,  g_f1_h);   cudaGetSymbolAddress((void**)&f1l,  g_f1_l);
    cudaGetSymbolAddress((void**)&f23h, g_f23_h);  cudaGetSymbolAddress((void**)&f23l, g_f23_l);
    cudaGetSymbolAddress((void**)&woh,  g_WoS_h);  cudaGetSymbolAddress((void**)&wol,  g_WoS_l);
    cudaGetSymbolAddress((void**)&cah,  g_cA_h);   cudaGetSymbolAddress((void**)&cal,  g_cA_l);
    cudaGetSymbolAddress((void**)&cbh,  g_cB_h);   cudaGetSymbolAddress((void**)&cbl,  g_cB_l);
    cudaGetSymbolAddress((void**)&pxres, g_xres);
    cudaGetSymbolAddress((void**)&pbc,   g_bc);
    cudaGetSymbolAddress((void**)&pb15,  g_b15);
    cudaGetSymbolAddress((void**)&pb23,  g_b23);
    cudaGetSymbolAddress((void**)&ps,    g_s);

    // launch 0: all prep
    k_prep<<<12221, 256>>>(W_in, W_D, W_cl, fc1_w, W_out, fc2_w, fc3_w, conv_w,
                           b_in, b_D, fc2_b, fc3_b);
    // 1-3: embed + norms
    k_embed<<<ROWS, 256>>>(ids, emb);
    k_samplestats<<<BATCH, 256>>>();
    k_norm<<<ROWS, 256>>>(rms_w);

    // launch 4 — GEMM1+5 (EPI4): scatter conv operand + xres
    k_tcW<4><<<dim3(N2X/256, ROWS/128, 1), 256, WSMEM>>>(
        xnh, xnl, w15h, w15l, pb15, nullptr, cbh, cbl,
        nullptr, nullptr, pxres, nullptr,
        DMODEL, N2X, 0, 0, 0);

    // launch 5 — conv GEMM (EPI1): xca = silu(cA @ cB + conv_b[row]) (ncu lands here)
    k_tcW<1><<<dim3(D2V/256, LSEQ/128, BATCH), 256, WSMEM>>>(
        cah, cal, cbh, cbl, nullptr, conv_b, xcah, xcal,
        nullptr, nullptr, nullptr, nullptr,
        K3, D2V, 0, (long)K3*D2V, (long)LSEQ*D2V);

    // launch 6 — GEMM3 (EPI2): xco split = xca @ W_cl + b_cl
    k_tcW<2><<<dim3(D2V/256, ROWS/128, 1), 256, WSMEM>>>(
        xcah, xcal, wclh, wcll, b_cl, nullptr, xcoh, xcol,
        nullptr, nullptr, nullptr, nullptr,
        D2V, D2V, 0, 0, 0);

    // launch 7 — side GEMM: [Bm|Cm] = xco @ [fc2|fc3] + [b2|b3]
    k_tcS<<<dim3(1, ROWS/128), 256, SSMEM>>>(xcoh, xcol, f23h, f23l, pb23, pbc, D2V);

    // launch 8 — s[row]
    k_s<<<ROWS, 32>>>();

    // launch 9 — GEMM4 (EPI5): prod split = silu(xco*softplus(xco@fc1+b1)*s) * silu(xres)
    k_tcW<5><<<dim3(D2V/256, ROWS/128, 1), 256, WSMEM>>>(
        xcoh, xcol, f1h, f1l, fc1_b, nullptr, prh, prl,
        xcoh, xcol, pxres, ps,
        D2V, D2V, 0, 0, 0);

    // launch 10 — GEMM6: out = prod @ W_out + b_out
    k_tcN<<<dim3(DMODEL/BN, ROWS/BM, 1), 256, NSMEM>>>(
        prh, prl, woh, wol, b_out, out, D2V, DMODEL);

    if (out_size >= ROWS * DMODEL + BATCH * DMODEL)
        k_maxpool<<<dim3((DMODEL + 255) / 256, BATCH), 256>>>(out, out + (size_t)ROWS * DMODEL);
}

// round 9
// speedup vs baseline: 1.0187x; 1.0187x over previous
#include <cuda_runtime.h>
#include <cuda_bf16.h>
#include <math.h>
#include <float.h>
#include <stdint.h>

#define BATCH 8
#define LSEQ 1024
#define DMODEL 768
#define D2V 1536
#define N2X 3072
#define NSTATE 16
#define ROWS (BATCH*LSEQ)
#define K3 (3*LSEQ)

// narrow kernel (128x128) for GEMM6
#define BM 128
#define BN 128
#define NSTAGES 3
#define NSTAGE_BYTES 65536u
#define NSMEM (NSTAGES*NSTAGE_BYTES)

// wide kernel (128x256)
#define WSTAGE 98304u
#define WOFF_AL 16384u
#define WOFF_BH 32768u
#define WOFF_BL 65536u
#define WSMEM (2u*WSTAGE)

// side kernel (128x32)
#define SSTAGE 40960u
#define SOFF_AL 16384u
#define SOFF_BH 32768u
#define SOFF_BL 36864u
#define SSMEM (3u*SSTAGE)

typedef __nv_bfloat16 bf16;

// ------------------------- device scratch -------------------------
__device__ float g_x   [ROWS*DMODEL];
__device__ float g_xpr [(size_t)ROWS*N2X];   // [xp | xres_raw] fp32
__device__ float g_bc  [ROWS*32];
__device__ float g_rowsum[ROWS];
__device__ float g_rowsq [ROWS];
__device__ float g_mu  [BATCH];
__device__ float g_rsig[BATCH];
__device__ float g_s   [ROWS];
__device__ float g_b15 [N2X];
__device__ float g_b23 [32];

__device__ bf16 g_xnP_h [ROWS*DMODEL], g_xnP_l [ROWS*DMODEL];
__device__ bf16 g_xcaP_h[ROWS*D2V],    g_xcaP_l[ROWS*D2V];
__device__ bf16 g_xcoP_h[ROWS*D2V],    g_xcoP_l[ROWS*D2V];
__device__ bf16 g_prP_h [ROWS*D2V],    g_prP_l [ROWS*D2V];
__device__ bf16 g_W15_h [DMODEL*N2X],  g_W15_l [DMODEL*N2X];
__device__ bf16 g_WclS_h[D2V*D2V],     g_WclS_l[D2V*D2V];
__device__ bf16 g_f1_h  [D2V*D2V],     g_f1_l  [D2V*D2V];
__device__ bf16 g_f23_h [D2V*32],      g_f23_l [D2V*32];
__device__ bf16 g_WoS_h [D2V*DMODEL],  g_WoS_l [D2V*DMODEL];
__device__ bf16 g_cA_h  [LSEQ*K3],     g_cA_l  [LSEQ*K3];
__device__ bf16 g_cB_h  [(size_t)BATCH*K3*D2V];
__device__ bf16 g_cB_l  [(size_t)BATCH*K3*D2V];

// ------------------------- helpers -------------------------
__device__ __forceinline__ float siluf(float v){ return v / (1.f + expf(-v)); }
__device__ __forceinline__ float softplusf(float v){ return (v > 20.f) ? v : log1pf(expf(v)); }

__device__ __forceinline__ uint32_t smem_u32(const void* p){
    uint32_t a;
    asm("{ .reg .u64 t; cvta.to.shared.u64 t, %1; cvt.u32.u64 %0, t; }" : "=r"(a) : "l"(p));
    return a;
}
__device__ __forceinline__ void cpa16(uint32_t dst, const void* src){
    asm volatile("cp.async.cg.shared.global [%0], [%1], 16;" :: "r"(dst), "l"(src) : "memory");
}
#define CP_COMMIT() asm volatile("cp.async.commit_group;" ::: "memory")
#define CP_WAIT(n)  asm volatile("cp.async.wait_group %0;" :: "n"(n) : "memory")

__device__ __forceinline__ void ldsm4(uint32_t addr, uint32_t* r){
    asm volatile("ldmatrix.sync.aligned.m8n8.x4.shared.b16 {%0,%1,%2,%3}, [%4];"
        : "=r"(r[0]), "=r"(r[1]), "=r"(r[2]), "=r"(r[3]) : "r"(addr));
}
__device__ __forceinline__ void ldsm4t(uint32_t addr, uint32_t* r0, uint32_t* r1){
    asm volatile("ldmatrix.sync.aligned.m8n8.x4.trans.shared.b16 {%0,%1,%2,%3}, [%4];"
        : "=r"(r0[0]), "=r"(r0[1]), "=r"(r1[0]), "=r"(r1[1]) : "r"(addr));
}
__device__ __forceinline__ void mma16816(float* d, const uint32_t* a, const uint32_t* b){
    asm volatile("mma.sync.aligned.m16n8k16.row.col.f32.bf16.bf16.f32 "
        "{%0,%1,%2,%3}, {%4,%5,%6,%7}, {%8,%9}, {%0,%1,%2,%3};"
        : "+f"(d[0]), "+f"(d[1]), "+f"(d[2]), "+f"(d[3])
        : "r"(a[0]), "r"(a[1]), "r"(a[2]), "r"(a[3]), "r"(b[0]), "r"(b[1]));
}
__device__ __forceinline__ void splitf(float v, bf16& h, bf16& l){
    h = __float2bfloat16(v);
    l = __float2bfloat16(v - __bfloat162float(h));
}

// ------------------------- WIDE HMMA GEMM 128x256 -------------------------
// EPI: 0 = fp32 out (GEMM1+5, pitch N)
//      1 = conv: silu + biasM, split out
//      2 = biasN, split out (GEMM3)
//      5 = GEMM4: delta=softplus -> fused prod epilogue, split out
template<int EPI>
__global__ void __launch_bounds__(256, 1) k_tcW(
    const bf16* __restrict__ Ah, const bf16* __restrict__ Al,
    const bf16* __restrict__ Bh, const bf16* __restrict__ Bl,
    const float* __restrict__ biasN, const float* __restrict__ biasM,
    bf16* __restrict__ Ch, bf16* __restrict__ Cl,
    const bf16* __restrict__ Xh, const bf16* __restrict__ Xl,
    float* __restrict__ Xf, const float* __restrict__ Sv,
    int K, int N, long sA, long sB, long sC)
{
    extern __shared__ char smem[];
    const int tid  = threadIdx.x;
    const int wid  = tid >> 5, lane = tid & 31;
    const int wm   = wid & 1,  wn = wid >> 1;
    const int row0 = blockIdx.y * 128;
    const int col0 = blockIdx.x * 256;
    Ah += (size_t)blockIdx.z * sA;  Al += (size_t)blockIdx.z * sA;
    Bh += (size_t)blockIdx.z * sB;  Bl += (size_t)blockIdx.z * sB;
    if (Ch){ Ch += (size_t)blockIdx.z * sC; Cl += (size_t)blockIdx.z * sC; }
    const int NK = K >> 6;
    const uint32_t sbase = smem_u32(smem);

    float acc[4][8][4];
    #pragma unroll
    for (int mi = 0; mi < 4; mi++)
        #pragma unroll
        for (int nj = 0; nj < 8; nj++)
            #pragma unroll
            for (int q = 0; q < 4; q++) acc[mi][nj][q] = 0.f;

    auto fill = [&](int kc, int s){
        uint32_t st = sbase + (uint32_t)s * WSTAGE;
        const bf16* ap[2] = { Ah, Al };
        #pragma unroll
        for (int arr = 0; arr < 2; arr++){
            uint32_t base = st + arr * WOFF_AL;
            #pragma unroll
            for (int it = 0; it < 4; it++){
                int id = tid + it * 256;
                int r = id >> 3, u = id & 7;
                cpa16(base + r * 128 + (((uint32_t)(u ^ (r & 7))) << 4),
                      ap[arr] + (size_t)(row0 + r) * K + kc * 64 + u * 8);
            }
        }
        const bf16* bp[2] = { Bh, Bl };
        #pragma unroll
        for (int arr = 0; arr < 2; arr++){
            uint32_t base = st + WOFF_BH + arr * (WOFF_BL - WOFF_BH);
            #pragma unroll
            for (int it = 0; it < 8; it++){
                int id = tid + it * 256;
                int k = id >> 5, u = id & 31;
                cpa16(base + k * 512 + (((uint32_t)(u ^ (k & 7))) << 4),
                      bp[arr] + (size_t)(kc * 64 + k) * N + col0 + u * 8);
            }
        }
        CP_COMMIT();
    };

    fill(0, 0);
    fill(1, 1);

    for (int kc = 0; kc < NK; kc++){
        int s = kc & 1;
        CP_WAIT(1);
        __syncthreads();

        uint32_t aAh = sbase + (uint32_t)s * WSTAGE;
        uint32_t aAl = aAh + WOFF_AL;
        uint32_t aBh = aAh + WOFF_BH;
        uint32_t aBl = aAh + WOFF_BL;

        #pragma unroll
        for (int ks = 0; ks < 4; ks++){
            uint32_t ah[4][4], al[4][4];
            const int au = 2 * ks + (lane >> 4);
            #pragma unroll
            for (int mi = 0; mi < 4; mi++){
                int r = wm * 64 + mi * 16 + (lane & 15);
                uint32_t off = r * 128 + (((uint32_t)(au ^ (r & 7))) << 4);
                ldsm4(aAh + off, ah[mi]);
                ldsm4(aAl + off, al[mi]);
            }
            const int bk = ks * 16 + (lane & 15);
            #pragma unroll
            for (int p = 0; p < 4; p++){
                int u = wn * 8 + p * 2 + (lane >> 4);
                uint32_t off = bk * 512 + (((uint32_t)(u ^ (bk & 7))) << 4);
                uint32_t b0[2], b1[2];
                ldsm4t(aBh + off, b0, b1);
                #pragma unroll
                for (int mi = 0; mi < 4; mi++){
                    mma16816(acc[mi][2*p],   ah[mi], b0);
                    mma16816(acc[mi][2*p+1], ah[mi], b1);
                }
                #pragma unroll
                for (int mi = 0; mi < 4; mi++){
                    mma16816(acc[mi][2*p],   al[mi], b0);
                    mma16816(acc[mi][2*p+1], al[mi], b1);
                }
            }
            #pragma unroll
            for (int p = 0; p < 4; p++){
                int u = wn * 8 + p * 2 + (lane >> 4);
                uint32_t off = bk * 512 + (((uint32_t)(u ^ (bk & 7))) << 4);
                uint32_t b0[2], b1[2];
                ldsm4t(aBl + off, b0, b1);
                #pragma unroll
                for (int mi = 0; mi < 4; mi++){
                    mma16816(acc[mi][2*p],   ah[mi], b0);
                    mma16816(acc[mi][2*p+1], ah[mi], b1);
                }
            }
        }

        __syncthreads();
        if (kc + 2 < NK) fill(kc + 2, s);
        else CP_COMMIT();
    }

    CP_WAIT(0);
    __syncthreads();

    // ---- epilogue: acc -> smem (260-pitch) -> global
    float* sf = (float*)smem;
    {
        const int rlo = lane >> 2;
        const int ncl = (lane & 3) * 2;
        #pragma unroll
        for (int mi = 0; mi < 4; mi++)
            #pragma unroll
            for (int nj = 0; nj < 8; nj++){
                int m = wm * 64 + mi * 16 + rlo;
                int n = wn * 64 + nj * 8 + ncl;
                *(float2*)&sf[(size_t)m * 260 + n]       = make_float2(acc[mi][nj][0], acc[mi][nj][1]);
                *(float2*)&sf[(size_t)(m + 8) * 260 + n] = make_float2(acc[mi][nj][2], acc[mi][nj][3]);
            }
    }
    __syncthreads();

    for (int i = tid; i < 128 * 64; i += 256){
        int r = i >> 6, c = (i & 63) * 4;
        int row = row0 + r;
        int col = col0 + c;
        float4 v4 = *(float4*)&sf[(size_t)r * 260 + c];
        float vv[4] = { v4.x, v4.y, v4.z, v4.w };

        if (EPI == 0){
            #pragma unroll
            for (int j = 0; j < 4; j++) vv[j] += __ldg(biasN + col + j);
            *(float4*)(Xf + (size_t)row * N + col) = make_float4(vv[0], vv[1], vv[2], vv[3]);
        }
        else if (EPI == 1){
            float bm = __ldg(biasM + row);
            #pragma unroll
            for (int j = 0; j < 4; j++) vv[j] = siluf(vv[j] + bm);
            bf16 hh[4], ll[4];
            #pragma unroll
            for (int j = 0; j < 4; j++) splitf(vv[j], hh[j], ll[j]);
            size_t o = (size_t)row * N + col;
            *(uint2*)(Ch + o) = *(uint2*)hh;
            *(uint2*)(Cl + o) = *(uint2*)ll;
        }
        else if (EPI == 2){
            #pragma unroll
            for (int j = 0; j < 4; j++) vv[j] += __ldg(biasN + col + j);
            bf16 hh[4], ll[4];
            #pragma unroll
            for (int j = 0; j < 4; j++) splitf(vv[j], hh[j], ll[j]);
            size_t o = (size_t)row * N + col;
            *(uint2*)(Ch + o) = *(uint2*)hh;
            *(uint2*)(Cl + o) = *(uint2*)ll;
        }
        else if (EPI == 5){
            float sv = __ldg(Sv + row);
            size_t o = (size_t)row * N + col;
            uint2 xh2 = __ldg((const uint2*)(Xh + o));
            uint2 xl2 = __ldg((const uint2*)(Xl + o));
            float4 xr4 = __ldg((const float4*)(Xf + (size_t)row * N2X + D2V + col));
            const bf16* xhp = (const bf16*)&xh2;
            const bf16* xlp = (const bf16*)&xl2;
            const float* xrp = (const float*)&xr4;
            bf16 hh[4], ll[4];
            #pragma unroll
            for (int j = 0; j < 4; j++){
                float delta = softplusf(vv[j] + __ldg(biasN + col + j));
                float xco = __bfloat162float(xhp[j]) + __bfloat162float(xlp[j]);
                float pr = siluf(xco * delta * sv) * siluf(xrp[j]);
                splitf(pr, hh[j], ll[j]);
            }
            *(uint2*)(Ch + o) = *(uint2*)hh;
            *(uint2*)(Cl + o) = *(uint2*)ll;
        }
    }
}

// ------------------------- NARROW HMMA GEMM 128x128 (GEMM6) ----
__global__ void __launch_bounds__(256, 1) k_tcN(
    const bf16* __restrict__ Ah, const bf16* __restrict__ Al,
    const bf16* __restrict__ Bh, const bf16* __restrict__ Bl,
    const float* __restrict__ biasN,
    float* __restrict__ C, int K, int N)
{
    extern __shared__ char smem[];
    const int tid  = threadIdx.x;
    const int wid  = tid >> 5, lane = tid & 31;
    const int wm   = wid & 3,  wn = wid >> 2;
    const int row0 = blockIdx.y * BM;
    const int col0 = blockIdx.x * BN;
    const int NK = K >> 6;
    const uint32_t sbase = smem_u32(smem);

    float acc[2][8][4];
    #pragma unroll
    for (int mi = 0; mi < 2; mi++)
        #pragma unroll
        for (int nj = 0; nj < 8; nj++)
            #pragma unroll
            for (int q = 0; q < 4; q++) acc[mi][nj][q] = 0.f;

    auto fill = [&](int kc, int s){
        uint32_t st = sbase + (uint32_t)s * NSTAGE_BYTES;
        const bf16* ap[2] = { Ah, Al };
        #pragma unroll
        for (int arr = 0; arr < 2; arr++){
            uint32_t base = st + arr * 16384u;
            #pragma unroll
            for (int it = 0; it < 4; it++){
                int id = tid + it * 256;
                int r = id >> 3, u = id & 7;
                cpa16(base + r * 128 + (((uint32_t)(u ^ (r & 7))) << 4),
                      ap[arr] + (size_t)(row0 + r) * K + kc * 64 + u * 8);
            }
        }
        const bf16* bp[2] = { Bh, Bl };
        #pragma unroll
        for (int arr = 0; arr < 2; arr++){
            uint32_t base = st + 32768u + arr * 16384u;
            #pragma unroll
            for (int it = 0; it < 4; it++){
                int id = tid + it * 256;
                int k = id >> 4, u = id & 15;
                cpa16(base + k * 256 + (((uint32_t)(u ^ (k & 7))) << 4),
                      bp[arr] + (size_t)(kc * 64 + k) * N + col0 + u * 8);
            }
        }
        CP_COMMIT();
    };

    fill(0, 0);
    if (NK > 1) fill(1, 1); else CP_COMMIT();

    for (int kc = 0; kc < NK; kc++){
        int s = kc % NSTAGES;
        CP_WAIT(1);
        __syncthreads();

        uint32_t aAh = sbase + (uint32_t)s * NSTAGE_BYTES;
        uint32_t aAl = aAh + 16384u;
        uint32_t aBh = aAh + 32768u;
        uint32_t aBl = aAh + 49152u;

        #pragma unroll
        for (int ks = 0; ks < 4; ks++){
            uint32_t ah[2][4], al[2][4], bb[8][2];
            const int arow = wm * 32 + (lane & 15);
            const int au   = 2 * ks + (lane >> 4);
            #pragma unroll
            for (int mi = 0; mi < 2; mi++){
                int r = arow + mi * 16;
                uint32_t off = r * 128 + (((uint32_t)(au ^ (r & 7))) << 4);
                ldsm4(aAh + off, ah[mi]);
                ldsm4(aAl + off, al[mi]);
            }
            const int bk = ks * 16 + (lane & 15);
            #pragma unroll
            for (int p = 0; p < 4; p++){
                int u = wn * 8 + p * 2 + (lane >> 4);
                uint32_t off = bk * 256 + (((uint32_t)(u ^ (bk & 7))) << 4);
                ldsm4t(aBh + off, bb[2*p], bb[2*p+1]);
            }
            #pragma unroll
            for (int mi = 0; mi < 2; mi++)
                #pragma unroll
                for (int nj = 0; nj < 8; nj++)
                    mma16816(acc[mi][nj], ah[mi], bb[nj]);
            #pragma unroll
            for (int mi = 0; mi < 2; mi++)
                #pragma unroll
                for (int nj = 0; nj < 8; nj++)
                    mma16816(acc[mi][nj], al[mi], bb[nj]);
            #pragma unroll
            for (int p = 0; p < 4; p++){
                int u = wn * 8 + p * 2 + (lane >> 4);
                uint32_t off = bk * 256 + (((uint32_t)(u ^ (bk & 7))) << 4);
                ldsm4t(aBl + off, bb[2*p], bb[2*p+1]);
            }
            #pragma unroll
            for (int mi = 0; mi < 2; mi++)
                #pragma unroll
                for (int nj = 0; nj < 8; nj++)
                    mma16816(acc[mi][nj], ah[mi], bb[nj]);
        }

        if (kc + 2 < NK) fill(kc + 2, (kc + 2) % NSTAGES);
        else CP_COMMIT();
    }

    __syncthreads();
    float* sf = (float*)smem;
    {
        const int mrow = wm * 32 + (lane >> 2);
        const int ncol = wn * 64 + (lane & 3) * 2;
        #pragma unroll
        for (int mi = 0; mi < 2; mi++)
            #pragma unroll
            for (int nj = 0; nj < 8; nj++){
                int m = mrow + mi * 16, n = ncol + nj * 8;
                *(float2*)&sf[(size_t)m * 132 + n]       = make_float2(acc[mi][nj][0], acc[mi][nj][1]);
                *(float2*)&sf[(size_t)(m + 8) * 132 + n] = make_float2(acc[mi][nj][2], acc[mi][nj][3]);
            }
    }
    __syncthreads();

    for (int i = tid; i < BM * (BN / 4); i += 256){
        int r = i >> 5, c = (i & 31) * 4;
        float4 v = *(float4*)&sf[(size_t)r * 132 + c];
        float vv[4] = { v.x, v.y, v.z, v.w };
        #pragma unroll
        for (int j = 0; j < 4; j++)
            vv[j] += __ldg(biasN + col0 + c + j);
        *(float4*)(C + (size_t)(row0 + r) * N + col0 + c) = make_float4(vv[0], vv[1], vv[2], vv[3]);
    }
}

// ------------------------- SIDE GEMM 128x32 (Bm|Cm) -------------------------
__global__ void __launch_bounds__(256, 1) k_tcS(
    const bf16* __restrict__ Ah, const bf16* __restrict__ Al,
    const bf16* __restrict__ Bh, const bf16* __restrict__ Bl,
    const float* __restrict__ biasN, float* __restrict__ C, int K)
{
    extern __shared__ char smem[];
    const int tid = threadIdx.x;
    const int wid = tid >> 5, lane = tid & 31;
    const int row0 = blockIdx.y * 128;
    const int NK = K >> 6;
    const uint32_t sbase = smem_u32(smem);

    float acc[4][4];
    #pragma unroll
    for (int nj = 0; nj < 4; nj++)
        #pragma unroll
        for (int q = 0; q < 4; q++) acc[nj][q] = 0.f;

    auto fill = [&](int kc, int s){
        uint32_t st = sbase + (uint32_t)s * SSTAGE;
        const bf16* ap[2] = { Ah, Al };
        #pragma unroll
        for (int arr = 0; arr < 2; arr++){
            uint32_t base = st + arr * SOFF_AL;
            #pragma unroll
            for (int it = 0; it < 4; it++){
                int id = tid + it * 256;
                int r = id >> 3, u = id & 7;
                cpa16(base + r * 128 + (((uint32_t)(u ^ (r & 7))) << 4),
                      ap[arr] + (size_t)(row0 + r) * K + kc * 64 + u * 8);
            }
        }
        const bf16* bp[2] = { Bh, Bl };
        #pragma unroll
        for (int arr = 0; arr < 2; arr++){
            uint32_t base = st + SOFF_BH + arr * (SOFF_BL - SOFF_BH);
            int k = tid >> 2, u = tid & 3;
            cpa16(base + k * 64 + (((uint32_t)(u ^ (k & 3))) << 4),
                  bp[arr] + (size_t)(kc * 64 + k) * 32 + u * 8);
        }
        CP_COMMIT();
    };

    fill(0, 0);
    fill(1, 1);

    for (int kc = 0; kc < NK; kc++){
        int s = kc % 3;
        CP_WAIT(1);
        __syncthreads();

        uint32_t aAh = sbase + (uint32_t)s * SSTAGE;
        uint32_t aAl = aAh + SOFF_AL;
        uint32_t aBh = aAh + SOFF_BH;
        uint32_t aBl = aAh + SOFF_BL;

        #pragma unroll
        for (int ks = 0; ks < 4; ks++){
            uint32_t ah[4], al[4], bh[4][2], bl[4][2];
            const int r = wid * 16 + (lane & 15);
            const int au = 2 * ks + (lane >> 4);
            uint32_t offA = r * 128 + (((uint32_t)(au ^ (r & 7))) << 4);
            ldsm4(aAh + offA, ah);
            ldsm4(aAl + offA, al);
            const int bk = ks * 16 + (lane & 15);
            #pragma unroll
            for (int p = 0; p < 2; p++){
                int u = p * 2 + (lane >> 4);
                uint32_t off = bk * 64 + (((uint32_t)(u ^ (bk & 3))) << 4);
                ldsm4t(aBh + off, bh[2*p], bh[2*p+1]);
                ldsm4t(aBl + off, bl[2*p], bl[2*p+1]);
            }
            #pragma unroll
            for (int nj = 0; nj < 4; nj++){
                mma16816(acc[nj], ah, bh[nj]);
                mma16816(acc[nj], al, bh[nj]);
                mma16816(acc[nj], ah, bl[nj]);
            }
        }

        __syncthreads();
        if (kc + 2 < NK) fill(kc + 2, (kc + 2) % 3);
        else CP_COMMIT();
    }

    {
        int mrow = wid * 16 + (lane >> 2);
        int ncol = (lane & 3) * 2;
        #pragma unroll
        for (int nj = 0; nj < 4; nj++){
            int n = nj * 8 + ncol;
            float b0 = __ldg(biasN + n), b1 = __ldg(biasN + n + 1);
            *(float2*)&C[(size_t)(row0 + mrow) * 32 + n]     = make_float2(acc[nj][0] + b0, acc[nj][1] + b1);
            *(float2*)&C[(size_t)(row0 + mrow + 8) * 32 + n] = make_float2(acc[nj][2] + b0, acc[nj][3] + b1);
        }
    }
}

// ------------------------- prep (all weight packs, one launch) -------------------------
__device__ __forceinline__ void wsplit_job(int lb, int tid, const float* W,
                                           bf16* Wh, bf16* Wl, int Nsrc, int Ndst, int off)
{
    size_t i4 = (size_t)lb * 256 + tid;
    int nq = Nsrc / 4;
    int k  = (int)(i4 / nq);
    int c  = (int)(i4 % nq) * 4;
    float4 v = *(const float4*)(W + (size_t)k * Nsrc + c);
    bf16 hh[4], ll[4];
    splitf(v.x, hh[0], ll[0]); splitf(v.y, hh[1], ll[1]);
    splitf(v.z, hh[2], ll[2]); splitf(v.w, hh[3], ll[3]);
    size_t o = (size_t)k * Ndst + off + c;
    *(uint2*)(Wh + o) = *(uint2*)hh;
    *(uint2*)(Wl + o) = *(uint2*)ll;
}

__global__ void k_prep(const float* __restrict__ W_in, const float* __restrict__ W_D,
                       const float* __restrict__ W_cl, const float* __restrict__ fc1_w,
                       const float* __restrict__ W_out,
                       const float* __restrict__ fc2_w, const float* __restrict__ fc3_w,
                       const float* __restrict__ conv_w,
                       const float* __restrict__ b_in, const float* __restrict__ b_D,
                       const float* __restrict__ fc2_b, const float* __restrict__ fc3_b)
{
    int bid = blockIdx.x;
    int tid = threadIdx.x;
    if (bid < 1152){ wsplit_job(bid, tid, W_in, g_W15_h, g_W15_l, D2V, N2X, 0); return; }
    bid -= 1152;
    if (bid < 1152){ wsplit_job(bid, tid, W_D, g_W15_h, g_W15_l, D2V, N2X, D2V); return; }
    bid -= 1152;
    if (bid < 2304){ wsplit_job(bid, tid, W_cl, g_WclS_h, g_WclS_l, D2V, D2V, 0); return; }
    bid -= 2304;
    if (bid < 2304){ wsplit_job(bid, tid, fc1_w, g_f1_h, g_f1_l, D2V, D2V, 0); return; }
    bid -= 2304;
    if (bid < 1152){ wsplit_job(bid, tid, W_out, g_WoS_h, g_WoS_l, DMODEL, DMODEL, 0); return; }
    bid -= 1152;
    if (bid < 24){ wsplit_job(bid, tid, fc2_w, g_f23_h, g_f23_l, NSTATE, 32, 0); return; }
    bid -= 24;
    if (bid < 24){ wsplit_job(bid, tid, fc3_w, g_f23_h, g_f23_l, NSTATE, 32, NSTATE); return; }
    bid -= 24;
    if (bid < 4096){
        int o = bid >> 2;
        int i = (bid & 3) * 256 + tid;
        #pragma unroll
        for (int k = 0; k < 3; k++){
            float v = conv_w[(size_t)o * K3 + 3 * i + k];
            bf16 h, l; splitf(v, h, l);
            size_t off = (size_t)o * K3 + k * 1024 + i;
            g_cA_h[off] = h; g_cA_l[off] = l;
        }
        return;
    }
    bid -= 4096;
    if (bid < 12){
        int i = bid * 256 + tid;
        g_b15[i] = (i < D2V) ? b_in[i] : b_D[i - D2V];
        return;
    }
    bid -= 12;
    if (tid < 32) g_b23[tid] = (tid < NSTATE) ? fc2_b[tid] : fc3_b[tid - NSTATE];
}

// ------------------------- aux kernels -------------------------
__global__ void k_embed(const int* __restrict__ ids, const float* __restrict__ emb)
{
    int row = blockIdx.x;
    int id  = ids[row];
    const float* src = emb + (size_t)id * DMODEL;
    float s = 0.f, ss = 0.f;
    for (int d = threadIdx.x; d < DMODEL; d += blockDim.x){
        float v = __ldg(src + d);
        g_x[(size_t)row * DMODEL + d] = v;
        s += v; ss += v * v;
    }
    __shared__ float sh[64];
    int lane = threadIdx.x & 31, w = threadIdx.x >> 5;
    #pragma unroll
    for (int o = 16; o; o >>= 1){
        s  += __shfl_down_sync(0xffffffffu, s,  o);
        ss += __shfl_down_sync(0xffffffffu, ss, o);
    }
    if (!lane){ sh[w] = s; sh[32 + w] = ss; }
    __syncthreads();
    if (threadIdx.x == 0){
        float S = 0.f, SS = 0.f;
        int nw = blockDim.x >> 5;
        for (int i = 0; i < nw; i++){ S += sh[i]; SS += sh[32 + i]; }
        g_rowsum[row] = S; g_rowsq[row] = SS;
    }
}

__global__ void k_samplestats()
{
    int b = blockIdx.x;
    float s = 0.f, ss = 0.f;
    for (int r = threadIdx.x; r < LSEQ; r += blockDim.x){
        s += g_rowsum[b * LSEQ + r]; ss += g_rowsq[b * LSEQ + r];
    }
    __shared__ float sh[64];
    int lane = threadIdx.x & 31, w = threadIdx.x >> 5;
    #pragma unroll
    for (int o = 16; o; o >>= 1){
        s  += __shfl_down_sync(0xffffffffu, s,  o);
        ss += __shfl_down_sync(0xffffffffu, ss, o);
    }
    if (!lane){ sh[w] = s; sh[32 + w] = ss; }
    __syncthreads();
    if (threadIdx.x == 0){
        float S = 0.f, SS = 0.f;
        int nw = blockDim.x >> 5;
        for (int i = 0; i < nw; i++){ S += sh[i]; SS += sh[32 + i]; }
        float inv = 1.f / ((float)LSEQ * (float)DMODEL);
        float mu  = S * inv;
        float var = SS * inv - mu * mu;
        g_mu[b]   = mu;
        g_rsig[b] = rsqrtf(var + 1e-5f);
    }
}

__global__ void k_norm(const float* __restrict__ rms_w)
{
    int row = blockIdx.x;
    int b = row >> 10;
    float mu = g_mu[b], rs = g_rsig[b];
    float msq = rs * rs * (g_rowsq[row] - 2.f * mu * g_rowsum[row] + (float)DMODEL * mu * mu) / (float)DMODEL;
    float a = rs * rsqrtf(msq + 1e-5f);
    const float* xr = g_x + (size_t)row * DMODEL;
    for (int d = threadIdx.x; d < DMODEL; d += blockDim.x){
        float v = (xr[d] - mu) * a * rms_w[d];
        bf16 h, l; splitf(v, h, l);
        g_xnP_h[(size_t)row * DMODEL + d] = h;
        g_xnP_l[(size_t)row * DMODEL + d] = l;
    }
}

// conv B gather (vectorized): cB[b][k*1024+i][t] = xp[b][i][t+k-1]; xp = g_xpr cols 0-1535
__global__ void k_convB()
{
    int t4 = threadIdx.x * 4;
    int i  = blockIdx.x;
    int zk = blockIdx.y;
    int b = zk / 3, k = zk % 3;
    const float* src = g_xpr + ((size_t)(b * LSEQ) + i) * N2X;
    bf16 hh[4], ll[4];
    #pragma unroll
    for (int j = 0; j < 4; j++){
        int tt = t4 + j + k - 1;
        float v = (tt >= 0 && tt < D2V) ? src[tt] : 0.f;
        splitf(v, hh[j], ll[j]);
    }
    size_t o = (size_t)b * K3 * D2V + (size_t)(k * 1024 + i) * D2V + t4;
    *(uint2*)(g_cB_h + o) = *(uint2*)hh;
    *(uint2*)(g_cB_l + o) = *(uint2*)ll;
}

__global__ void k_s()
{
    int row = blockIdx.x;
    int lane = threadIdx.x;
    float p = 0.f;
    if (lane < NSTATE){
        float bm = g_bc[(size_t)row * 32 + lane];
        float cm = g_bc[(size_t)row * 32 + NSTATE + lane];
        p = bm * cm;
    }
    #pragma unroll
    for (int o = 8; o; o >>= 1) p += __shfl_xor_sync(0xffffffffu, p, o);
    if (lane == 0) g_s[row] = p;
}

__global__ void k_maxpool(const float* __restrict__ out, float* __restrict__ pooled)
{
    int b = blockIdx.y;
    int d = blockIdx.x * blockDim.x + threadIdx.x;
    if (d >= DMODEL) return;
    const float* p = out + (size_t)b * LSEQ * DMODEL + d;
    float m = -FLT_MAX;
    for (int l = 0; l < LSEQ; l++) m = fmaxf(m, p[(size_t)l * DMODEL]);
    pooled[b * DMODEL + d] = m;
}

// ------------------------- launch -------------------------
extern "C" void kernel_launch(void* const* d_in, const int* in_sizes, int n_in,
                              void* d_out, int out_size)
{
    const int*   ids    = (const int*)  d_in[0];
    const float* emb    = (const float*)d_in[1];
    const float* rms_w  = (const float*)d_in[2];
    const float* W_in   = (const float*)d_in[3];
    const float* b_in   = (const float*)d_in[4];
    const float* conv_w = (const float*)d_in[5];
    const float* conv_b = (const float*)d_in[6];
    const float* W_cl   = (const float*)d_in[7];
    const float* b_cl   = (const float*)d_in[8];
    const float* fc1_w  = (const float*)d_in[9];
    const float* fc1_b  = (const float*)d_in[10];
    const float* fc2_w  = (const float*)d_in[11];
    const float* fc2_b  = (const float*)d_in[12];
    const float* fc3_w  = (const float*)d_in[13];
    const float* fc3_b  = (const float*)d_in[14];
    const float* W_D    = (const float*)d_in[16];
    const float* b_D    = (const float*)d_in[17];
    const float* W_out  = (const float*)d_in[18];
    const float* b_out  = (const float*)d_in[19];
    float* out = (float*)d_out;

    cudaFuncSetAttribute(k_tcW<0>, cudaFuncAttributeMaxDynamicSharedMemorySize, WSMEM);
    cudaFuncSetAttribute(k_tcW<1>, cudaFuncAttributeMaxDynamicSharedMemorySize, WSMEM);
    cudaFuncSetAttribute(k_tcW<2>, cudaFuncAttributeMaxDynamicSharedMemorySize, WSMEM);
    cudaFuncSetAttribute(k_tcW<5>, cudaFuncAttributeMaxDynamicSharedMemorySize, WSMEM);
    cudaFuncSetAttribute(k_tcN,    cudaFuncAttributeMaxDynamicSharedMemorySize, NSMEM);
    cudaFuncSetAttribute(k_tcS,    cudaFuncAttributeMaxDynamicSharedMemorySize, SSMEM);

    bf16 *xnh, *xnl, *xcah, *xcal, *xcoh, *xcol, *prh, *prl;
    bf16 *w15h, *w15l, *wclh, *wcll, *f1h, *f1l, *f23h, *f23l, *woh, *wol;
    bf16 *cah, *cal, *cbh, *cbl;
    float *pxpr, *pbc, *pb15, *pb23, *ps;
    cudaGetSymbolAddress((void**)&xnh,  g_xnP_h);  cudaGetSymbolAddress((void**)&xnl,  g_xnP_l);
    cudaGetSymbolAddress((void**)&xcah, g_xcaP_h); cudaGetSymbolAddress((void**)&xcal, g_xcaP_l);
    cudaGetSymbolAddress((void**)&xcoh, g_xcoP_h); cudaGetSymbolAddress((void**)&xcol, g_xcoP_l);
    cudaGetSymbolAddress((void**)&prh,  g_prP_h);  cudaGetSymbolAddress((void**)&prl,  g_prP_l);
    cudaGetSymbolAddress((void**)&w15h, g_W15_h);  cudaGetSymbolAddress((void**)&w15l, g_W15_l);
    cudaGetSymbolAddress((void**)&wclh, g_WclS_h); cudaGetSymbolAddress((void**)&wcll, g_WclS_l);
    cudaGetSymbolAddress((void**)&f1h,  g_f1_h);   cudaGetSymbolAddress((void**)&f1l,  g_f1_l);
    cudaGetSymbolAddress((void**)&f23h, g_f23_h);  cudaGetSymbolAddress((void**)&f23l, g_f23_l);
    cudaGetSymbolAddress((void**)&woh,  g_WoS_h);  cudaGetSymbolAddress((void**)&wol,  g_WoS_l);
    cudaGetSymbolAddress((void**)&cah,  g_cA_h);   cudaGetSymbolAddress((void**)&cal,  g_cA_l);
    cudaGetSymbolAddress((void**)&cbh,  g_cB_h);   cudaGetSymbolAddress((void**)&cbl,  g_cB_l);
    cudaGetSymbolAddress((void**)&pxpr, g_xpr);
    cudaGetSymbolAddress((void**)&pbc,  g_bc);
    cudaGetSymbolAddress((void**)&pb15, g_b15);
    cudaGetSymbolAddress((void**)&pb23, g_b23);
    cudaGetSymbolAddress((void**)&ps,   g_s);

    // launch 0: all prep
    k_prep<<<12221, 256>>>(W_in, W_D, W_cl, fc1_w, W_out, fc2_w, fc3_w, conv_w,
                           b_in, b_D, fc2_b, fc3_b);
    // 1-3: embed + norms
    k_embed<<<ROWS, 256>>>(ids, emb);
    k_samplestats<<<BATCH, 256>>>();
    k_norm<<<ROWS, 256>>>(rms_w);

    // GEMM1+5 (EPI0): [xp | xres] = xn @ [W_in | W_D] + b  (fp32)
    k_tcW<0><<<dim3(N2X/256, ROWS/128, 1), 256, WSMEM>>>(
        xnh, xnl, w15h, w15l, pb15, nullptr, nullptr, nullptr,
        nullptr, nullptr, pxpr, nullptr,
        DMODEL, N2X, 0, 0, 0);

    // conv operand gather (vectorized, k-major)
    k_convB<<<dim3(LSEQ, 3*BATCH), 384>>>();

    // conv GEMM (EPI1): xca = silu(cA @ cB + conv_b[row]), split out
    k_tcW<1><<<dim3(D2V/256, LSEQ/128, BATCH), 256, WSMEM>>>(
        cah, cal, cbh, cbl, nullptr, conv_b, xcah, xcal,
        nullptr, nullptr, nullptr, nullptr,
        K3, D2V, 0, (long)K3*D2V, (long)LSEQ*D2V);

    // GEMM3 (EPI2): xco split = xca @ W_cl + b_cl
    k_tcW<2><<<dim3(D2V/256, ROWS/128, 1), 256, WSMEM>>>(
        xcah, xcal, wclh, wcll, b_cl, nullptr, xcoh, xcol,
        nullptr, nullptr, nullptr, nullptr,
        D2V, D2V, 0, 0, 0);

    // side GEMM: [Bm|Cm] = xco @ [fc2|fc3] + [b2|b3]
    k_tcS<<<dim3(1, ROWS/128), 256, SSMEM>>>(xcoh, xcol, f23h, f23l, pb23, pbc, D2V);

    // s[row]
    k_s<<<ROWS, 32>>>();

    // GEMM4 (EPI5): prod split = silu(xco*softplus(xco@fc1+b1)*s) * silu(xres)
    k_tcW<5><<<dim3(D2V/256, ROWS/128, 1), 256, WSMEM>>>(
        xcoh, xcol, f1h, f1l, fc1_b, nullptr, prh, prl,
        xcoh, xcol, pxpr, ps,
        D2V, D2V, 0, 0, 0);

    // GEMM6: out = prod @ W_out + b_out
    k_tcN<<<dim3(DMODEL/BN, ROWS/BM, 1), 256, NSMEM>>>(
        prh, prl, woh, wol, b_out, out, D2V, DMODEL);

    if (out_size >= ROWS * DMODEL + BATCH * DMODEL)
        k_maxpool<<<dim3((DMODEL + 255) / 256, BATCH), 256>>>(out, out + (size_t)ROWS * DMODEL);
}

// round 11
// speedup vs baseline: 1.0579x; 1.0385x over previous
#include <cuda_runtime.h>
#include <cuda_bf16.h>
#include <math.h>
#include <float.h>
#include <stdint.h>

#define BATCH 8
#define LSEQ 1024
#define DMODEL 768
#define D2V 1536
#define N2X 3072
#define NSTATE 16
#define ROWS (BATCH*LSEQ)
#define K3 (3*LSEQ)

// narrow kernel (128x128) for GEMM6
#define BM 128
#define BN 128
#define NSTAGES 3
#define NSTAGE_BYTES 65536u
#define NSMEM (NSTAGES*NSTAGE_BYTES)

// wide kernel (128x256)
#define WSTAGE 98304u
#define WOFF_AL 16384u
#define WOFF_BH 32768u
#define WOFF_BL 65536u
#define WSMEM (2u*WSTAGE)

// side kernel (128x32, K-split)
#define SSTAGE 40960u
#define SOFF_AL 16384u
#define SOFF_BH 32768u
#define SOFF_BL 36864u
#define SSMEM (3u*SSTAGE)
#define KSPLIT 4

typedef __nv_bfloat16 bf16;

// ------------------------- device scratch -------------------------
__device__ float g_x   [ROWS*DMODEL];
__device__ float g_xpr [(size_t)ROWS*N2X];   // [xp | xres_raw] fp32
__device__ float g_xco [(size_t)ROWS*D2V];
__device__ float g_dl  [(size_t)ROWS*D2V];
__device__ float g_bc  [(size_t)KSPLIT*ROWS*32];
__device__ float g_rowsum[ROWS];
__device__ float g_rowsq [ROWS];
__device__ float g_mu  [BATCH];
__device__ float g_rsig[BATCH];
__device__ float g_s   [ROWS];
__device__ float g_b15 [N2X];
__device__ float g_b23 [32];

__device__ bf16 g_xnP_h [ROWS*DMODEL], g_xnP_l [ROWS*DMODEL];
__device__ bf16 g_xcaP_h[ROWS*D2V],    g_xcaP_l[ROWS*D2V];
__device__ bf16 g_xcoP_h[ROWS*D2V],    g_xcoP_l[ROWS*D2V];
__device__ bf16 g_prP_h [ROWS*D2V],    g_prP_l [ROWS*D2V];
__device__ bf16 g_W15_h [DMODEL*N2X],  g_W15_l [DMODEL*N2X];
__device__ bf16 g_WclS_h[D2V*D2V],     g_WclS_l[D2V*D2V];
__device__ bf16 g_f1_h  [D2V*D2V],     g_f1_l  [D2V*D2V];
__device__ bf16 g_f23_h [D2V*32],      g_f23_l [D2V*32];
__device__ bf16 g_WoS_h [D2V*DMODEL],  g_WoS_l [D2V*DMODEL];
__device__ bf16 g_cA_h  [LSEQ*K3],     g_cA_l  [LSEQ*K3];
__device__ bf16 g_cB_h  [(size_t)BATCH*K3*D2V];
__device__ bf16 g_cB_l  [(size_t)BATCH*K3*D2V];

// ------------------------- helpers -------------------------
__device__ __forceinline__ float siluf(float v){ return v / (1.f + expf(-v)); }
__device__ __forceinline__ float softplusf(float v){ return (v > 20.f) ? v : log1pf(expf(v)); }

__device__ __forceinline__ uint32_t smem_u32(const void* p){
    uint32_t a;
    asm("{ .reg .u64 t; cvta.to.shared.u64 t, %1; cvt.u32.u64 %0, t; }" : "=r"(a) : "l"(p));
    return a;
}
__device__ __forceinline__ void cpa16(uint32_t dst, const void* src){
    asm volatile("cp.async.cg.shared.global [%0], [%1], 16;" :: "r"(dst), "l"(src) : "memory");
}
#define CP_COMMIT() asm volatile("cp.async.commit_group;" ::: "memory")
#define CP_WAIT(n)  asm volatile("cp.async.wait_group %0;" :: "n"(n) : "memory")

__device__ __forceinline__ void ldsm4(uint32_t addr, uint32_t* r){
    asm volatile("ldmatrix.sync.aligned.m8n8.x4.shared.b16 {%0,%1,%2,%3}, [%4];"
        : "=r"(r[0]), "=r"(r[1]), "=r"(r[2]), "=r"(r[3]) : "r"(addr));
}
__device__ __forceinline__ void ldsm4t(uint32_t addr, uint32_t* r0, uint32_t* r1){
    asm volatile("ldmatrix.sync.aligned.m8n8.x4.trans.shared.b16 {%0,%1,%2,%3}, [%4];"
        : "=r"(r0[0]), "=r"(r0[1]), "=r"(r1[0]), "=r"(r1[1]) : "r"(addr));
}
__device__ __forceinline__ void mma16816(float* d, const uint32_t* a, const uint32_t* b){
    asm volatile("mma.sync.aligned.m16n8k16.row.col.f32.bf16.bf16.f32 "
        "{%0,%1,%2,%3}, {%4,%5,%6,%7}, {%8,%9}, {%0,%1,%2,%3};"
        : "+f"(d[0]), "+f"(d[1]), "+f"(d[2]), "+f"(d[3])
        : "r"(a[0]), "r"(a[1]), "r"(a[2]), "r"(a[3]), "r"(b[0]), "r"(b[1]));
}
__device__ __forceinline__ void splitf(float v, bf16& h, bf16& l){
    h = __float2bfloat16(v);
    l = __float2bfloat16(v - __bfloat162float(h));
}

// ------------------------- WIDE HMMA GEMM 128x256 (R7-proven) -------------------------
// C = EPI(A@B + biasN + biasM). EPI: 0 none, 1 silu, 2 softplus.
// Writes fp32 C if C!=null; writes split Ch/Cl if SPLIT.
template<int EPI, bool SPLIT>
__global__ void __launch_bounds__(256, 1) k_tcW(
    const bf16* __restrict__ Ah, const bf16* __restrict__ Al,
    const bf16* __restrict__ Bh, const bf16* __restrict__ Bl,
    const float* __restrict__ biasN, const float* __restrict__ biasM,
    float* __restrict__ C, bf16* __restrict__ Ch, bf16* __restrict__ Cl,
    int K, int N, long sA, long sB, long sC)
{
    extern __shared__ char smem[];
    const int tid  = threadIdx.x;
    const int wid  = tid >> 5, lane = tid & 31;
    const int wm   = wid & 1,  wn = wid >> 1;
    const int row0 = blockIdx.y * 128;
    const int col0 = blockIdx.x * 256;
    Ah += (size_t)blockIdx.z * sA;  Al += (size_t)blockIdx.z * sA;
    Bh += (size_t)blockIdx.z * sB;  Bl += (size_t)blockIdx.z * sB;
    if (C) C += (size_t)blockIdx.z * sC;
    if (SPLIT){ Ch += (size_t)blockIdx.z * sC; Cl += (size_t)blockIdx.z * sC; }
    const int NK = K >> 6;
    const uint32_t sbase = smem_u32(smem);

    float acc[4][8][4];
    #pragma unroll
    for (int mi = 0; mi < 4; mi++)
        #pragma unroll
        for (int nj = 0; nj < 8; nj++)
            #pragma unroll
            for (int q = 0; q < 4; q++) acc[mi][nj][q] = 0.f;

    auto fill = [&](int kc, int s){
        uint32_t st = sbase + (uint32_t)s * WSTAGE;
        const bf16* ap[2] = { Ah, Al };
        #pragma unroll
        for (int arr = 0; arr < 2; arr++){
            uint32_t base = st + arr * WOFF_AL;
            #pragma unroll
            for (int it = 0; it < 4; it++){
                int id = tid + it * 256;
                int r = id >> 3, u = id & 7;
                cpa16(base + r * 128 + (((uint32_t)(u ^ (r & 7))) << 4),
                      ap[arr] + (size_t)(row0 + r) * K + kc * 64 + u * 8);
            }
        }
        const bf16* bp[2] = { Bh, Bl };
        #pragma unroll
        for (int arr = 0; arr < 2; arr++){
            uint32_t base = st + WOFF_BH + arr * (WOFF_BL - WOFF_BH);
            #pragma unroll
            for (int it = 0; it < 8; it++){
                int id = tid + it * 256;
                int k = id >> 5, u = id & 31;
                cpa16(base + k * 512 + (((uint32_t)(u ^ (k & 7))) << 4),
                      bp[arr] + (size_t)(kc * 64 + k) * N + col0 + u * 8);
            }
        }
        CP_COMMIT();
    };

    fill(0, 0);
    fill(1, 1);

    for (int kc = 0; kc < NK; kc++){
        int s = kc & 1;
        CP_WAIT(1);
        __syncthreads();

        uint32_t aAh = sbase + (uint32_t)s * WSTAGE;
        uint32_t aAl = aAh + WOFF_AL;
        uint32_t aBh = aAh + WOFF_BH;
        uint32_t aBl = aAh + WOFF_BL;

        #pragma unroll
        for (int ks = 0; ks < 4; ks++){
            uint32_t ah[4][4], al[4][4];
            const int au = 2 * ks + (lane >> 4);
            #pragma unroll
            for (int mi = 0; mi < 4; mi++){
                int r = wm * 64 + mi * 16 + (lane & 15);
                uint32_t off = r * 128 + (((uint32_t)(au ^ (r & 7))) << 4);
                ldsm4(aAh + off, ah[mi]);
                ldsm4(aAl + off, al[mi]);
            }
            const int bk = ks * 16 + (lane & 15);
            #pragma unroll
            for (int p = 0; p < 4; p++){
                int u = wn * 8 + p * 2 + (lane >> 4);
                uint32_t off = bk * 512 + (((uint32_t)(u ^ (bk & 7))) << 4);
                uint32_t b0[2], b1[2];
                ldsm4t(aBh + off, b0, b1);
                #pragma unroll
                for (int mi = 0; mi < 4; mi++){
                    mma16816(acc[mi][2*p],   ah[mi], b0);
                    mma16816(acc[mi][2*p+1], ah[mi], b1);
                }
                #pragma unroll
                for (int mi = 0; mi < 4; mi++){
                    mma16816(acc[mi][2*p],   al[mi], b0);
                    mma16816(acc[mi][2*p+1], al[mi], b1);
                }
            }
            #pragma unroll
            for (int p = 0; p < 4; p++){
                int u = wn * 8 + p * 2 + (lane >> 4);
                uint32_t off = bk * 512 + (((uint32_t)(u ^ (bk & 7))) << 4);
                uint32_t b0[2], b1[2];
                ldsm4t(aBl + off, b0, b1);
                #pragma unroll
                for (int mi = 0; mi < 4; mi++){
                    mma16816(acc[mi][2*p],   ah[mi], b0);
                    mma16816(acc[mi][2*p+1], ah[mi], b1);
                }
            }
        }

        __syncthreads();
        if (kc + 2 < NK) fill(kc + 2, s);
        else CP_COMMIT();
    }

    CP_WAIT(0);
    __syncthreads();

    // ---- epilogue: acc -> smem (260-pitch) -> global
    float* sf = (float*)smem;
    {
        const int rlo = lane >> 2;
        const int ncl = (lane & 3) * 2;
        #pragma unroll
        for (int mi = 0; mi < 4; mi++)
            #pragma unroll
            for (int nj = 0; nj < 8; nj++){
                int m = wm * 64 + mi * 16 + rlo;
                int n = wn * 64 + nj * 8 + ncl;
                *(float2*)&sf[(size_t)m * 260 + n]       = make_float2(acc[mi][nj][0], acc[mi][nj][1]);
                *(float2*)&sf[(size_t)(m + 8) * 260 + n] = make_float2(acc[mi][nj][2], acc[mi][nj][3]);
            }
    }
    __syncthreads();

    for (int i = tid; i < 128 * 64; i += 256){
        int r = i >> 6, c = (i & 63) * 4;
        int row = row0 + r;
        int col = col0 + c;
        float4 v4 = *(float4*)&sf[(size_t)r * 260 + c];
        float bm = biasM ? __ldg(biasM + row) : 0.f;
        float vv[4] = { v4.x, v4.y, v4.z, v4.w };
        #pragma unroll
        for (int j = 0; j < 4; j++){
            float t = vv[j] + bm + (biasN ? __ldg(biasN + col + j) : 0.f);
            if (EPI == 1) t = siluf(t);
            else if (EPI == 2) t = softplusf(t);
            vv[j] = t;
        }
        size_t o = (size_t)row * N + col;
        if (C) *(float4*)(C + o) = make_float4(vv[0], vv[1], vv[2], vv[3]);
        if (SPLIT){
            bf16 hh[4], ll[4];
            #pragma unroll
            for (int j = 0; j < 4; j++) splitf(vv[j], hh[j], ll[j]);
            *(uint2*)(Ch + o) = *(uint2*)hh;
            *(uint2*)(Cl + o) = *(uint2*)ll;
        }
    }
}

// ------------------------- NARROW HMMA GEMM 128x128 (GEMM6) ----
__global__ void __launch_bounds__(256, 1) k_tcN(
    const bf16* __restrict__ Ah, const bf16* __restrict__ Al,
    const bf16* __restrict__ Bh, const bf16* __restrict__ Bl,
    const float* __restrict__ biasN,
    float* __restrict__ C, int K, int N)
{
    extern __shared__ char smem[];
    const int tid  = threadIdx.x;
    const int wid  = tid >> 5, lane = tid & 31;
    const int wm   = wid & 3,  wn = wid >> 2;
    const int row0 = blockIdx.y * BM;
    const int col0 = blockIdx.x * BN;
    const int NK = K >> 6;
    const uint32_t sbase = smem_u32(smem);

    float acc[2][8][4];
    #pragma unroll
    for (int mi = 0; mi < 2; mi++)
        #pragma unroll
        for (int nj = 0; nj < 8; nj++)
            #pragma unroll
            for (int q = 0; q < 4; q++) acc[mi][nj][q] = 0.f;

    auto fill = [&](int kc, int s){
        uint32_t st = sbase + (uint32_t)s * NSTAGE_BYTES;
        const bf16* ap[2] = { Ah, Al };
        #pragma unroll
        for (int arr = 0; arr < 2; arr++){
            uint32_t base = st + arr * 16384u;
            #pragma unroll
            for (int it = 0; it < 4; it++){
                int id = tid + it * 256;
                int r = id >> 3, u = id & 7;
                cpa16(base + r * 128 + (((uint32_t)(u ^ (r & 7))) << 4),
                      ap[arr] + (size_t)(row0 + r) * K + kc * 64 + u * 8);
            }
        }
        const bf16* bp[2] = { Bh, Bl };
        #pragma unroll
        for (int arr = 0; arr < 2; arr++){
            uint32_t base = st + 32768u + arr * 16384u;
            #pragma unroll
            for (int it = 0; it < 4; it++){
                int id = tid + it * 256;
                int k = id >> 4, u = id & 15;
                cpa16(base + k * 256 + (((uint32_t)(u ^ (k & 7))) << 4),
                      bp[arr] + (size_t)(kc * 64 + k) * N + col0 + u * 8);
            }
        }
        CP_COMMIT();
    };

    fill(0, 0);
    if (NK > 1) fill(1, 1); else CP_COMMIT();

    for (int kc = 0; kc < NK; kc++){
        int s = kc % NSTAGES;
        CP_WAIT(1);
        __syncthreads();

        uint32_t aAh = sbase + (uint32_t)s * NSTAGE_BYTES;
        uint32_t aAl = aAh + 16384u;
        uint32_t aBh = aAh + 32768u;
        uint32_t aBl = aAh + 49152u;

        #pragma unroll
        for (int ks = 0; ks < 4; ks++){
            uint32_t ah[2][4], al[2][4], bb[8][2];
            const int arow = wm * 32 + (lane & 15);
            const int au   = 2 * ks + (lane >> 4);
            #pragma unroll
            for (int mi = 0; mi < 2; mi++){
                int r = arow + mi * 16;
                uint32_t off = r * 128 + (((uint32_t)(au ^ (r & 7))) << 4);
                ldsm4(aAh + off, ah[mi]);
                ldsm4(aAl + off, al[mi]);
            }
            const int bk = ks * 16 + (lane & 15);
            #pragma unroll
            for (int p = 0; p < 4; p++){
                int u = wn * 8 + p * 2 + (lane >> 4);
                uint32_t off = bk * 256 + (((uint32_t)(u ^ (bk & 7))) << 4);
                ldsm4t(aBh + off, bb[2*p], bb[2*p+1]);
            }
            #pragma unroll
            for (int mi = 0; mi < 2; mi++)
                #pragma unroll
                for (int nj = 0; nj < 8; nj++)
                    mma16816(acc[mi][nj], ah[mi], bb[nj]);
            #pragma unroll
            for (int mi = 0; mi < 2; mi++)
                #pragma unroll
                for (int nj = 0; nj < 8; nj++)
                    mma16816(acc[mi][nj], al[mi], bb[nj]);
            #pragma unroll
            for (int p = 0; p < 4; p++){
                int u = wn * 8 + p * 2 + (lane >> 4);
                uint32_t off = bk * 256 + (((uint32_t)(u ^ (bk & 7))) << 4);
                ldsm4t(aBl + off, bb[2*p], bb[2*p+1]);
            }
            #pragma unroll
            for (int mi = 0; mi < 2; mi++)
                #pragma unroll
                for (int nj = 0; nj < 8; nj++)
                    mma16816(acc[mi][nj], ah[mi], bb[nj]);
        }

        if (kc + 2 < NK) fill(kc + 2, (kc + 2) % NSTAGES);
        else CP_COMMIT();
    }

    __syncthreads();
    float* sf = (float*)smem;
    {
        const int mrow = wm * 32 + (lane >> 2);
        const int ncol = wn * 64 + (lane & 3) * 2;
        #pragma unroll
        for (int mi = 0; mi < 2; mi++)
            #pragma unroll
            for (int nj = 0; nj < 8; nj++){
                int m = mrow + mi * 16, n = ncol + nj * 8;
                *(float2*)&sf[(size_t)m * 132 + n]       = make_float2(acc[mi][nj][0], acc[mi][nj][1]);
                *(float2*)&sf[(size_t)(m + 8) * 132 + n] = make_float2(acc[mi][nj][2], acc[mi][nj][3]);
            }
    }
    __syncthreads();

    for (int i = tid; i < BM * (BN / 4); i += 256){
        int r = i >> 5, c = (i & 31) * 4;
        float4 v = *(float4*)&sf[(size_t)r * 132 + c];
        float vv[4] = { v.x, v.y, v.z, v.w };
        #pragma unroll
        for (int j = 0; j < 4; j++)
            vv[j] += __ldg(biasN + col0 + c + j);
        *(float4*)(C + (size_t)(row0 + r) * N + col0 + c) = make_float4(vv[0], vv[1], vv[2], vv[3]);
    }
}

// ------------------------- SIDE GEMM 128x32 K-split (Bm|Cm partials) ----------
// grid (KSPLIT, ROWS/128); writes raw partials (bias added in k_s)
__global__ void __launch_bounds__(256, 1) k_tcS(
    const bf16* __restrict__ Ah, const bf16* __restrict__ Al,
    const bf16* __restrict__ Bh, const bf16* __restrict__ Bl,
    float* __restrict__ C, int K)
{
    extern __shared__ char smem[];
    const int tid = threadIdx.x;
    const int wid = tid >> 5, lane = tid & 31;
    const int row0 = blockIdx.y * 128;
    const int kc0 = blockIdx.x * (K / KSPLIT / 64);   // 6 chunks per slice
    const int NK = K / KSPLIT / 64;                   // 6
    const uint32_t sbase = smem_u32(smem);
    C += (size_t)blockIdx.x * ROWS * 32;

    float acc[4][4];
    #pragma unroll
    for (int nj = 0; nj < 4; nj++)
        #pragma unroll
        for (int q = 0; q < 4; q++) acc[nj][q] = 0.f;

    auto fill = [&](int kc, int s){
        uint32_t st = sbase + (uint32_t)s * SSTAGE;
        const bf16* ap[2] = { Ah, Al };
        #pragma unroll
        for (int arr = 0; arr < 2; arr++){
            uint32_t base = st + arr * SOFF_AL;
            #pragma unroll
            for (int it = 0; it < 4; it++){
                int id = tid + it * 256;
                int r = id >> 3, u = id & 7;
                cpa16(base + r * 128 + (((uint32_t)(u ^ (r & 7))) << 4),
                      ap[arr] + (size_t)(row0 + r) * K + (kc0 + kc) * 64 + u * 8);
            }
        }
        const bf16* bp[2] = { Bh, Bl };
        #pragma unroll
        for (int arr = 0; arr < 2; arr++){
            uint32_t base = st + SOFF_BH + arr * (SOFF_BL - SOFF_BH);
            int k = tid >> 2, u = tid & 3;
            cpa16(base + k * 64 + (((uint32_t)(u ^ (k & 3))) << 4),
                  bp[arr] + (size_t)((kc0 + kc) * 64 + k) * 32 + u * 8);
        }
        CP_COMMIT();
    };

    fill(0, 0);
    fill(1, 1);

    for (int kc = 0; kc < NK; kc++){
        int s = kc % 3;
        CP_WAIT(1);
        __syncthreads();

        uint32_t aAh = sbase + (uint32_t)s * SSTAGE;
        uint32_t aAl = aAh + SOFF_AL;
        uint32_t aBh = aAh + SOFF_BH;
        uint32_t aBl = aAh + SOFF_BL;

        #pragma unroll
        for (int ks = 0; ks < 4; ks++){
            uint32_t ah[4], al[4], bh[4][2], bl[4][2];
            const int r = wid * 16 + (lane & 15);
            const int au = 2 * ks + (lane >> 4);
            uint32_t offA = r * 128 + (((uint32_t)(au ^ (r & 7))) << 4);
            ldsm4(aAh + offA, ah);
            ldsm4(aAl + offA, al);
            const int bk = ks * 16 + (lane & 15);
            #pragma unroll
            for (int p = 0; p < 2; p++){
                int u = p * 2 + (lane >> 4);
                uint32_t off = bk * 64 + (((uint32_t)(u ^ (bk & 3))) << 4);
                ldsm4t(aBh + off, bh[2*p], bh[2*p+1]);
                ldsm4t(aBl + off, bl[2*p], bl[2*p+1]);
            }
            #pragma unroll
            for (int nj = 0; nj < 4; nj++){
                mma16816(acc[nj], ah, bh[nj]);
                mma16816(acc[nj], al, bh[nj]);
                mma16816(acc[nj], ah, bl[nj]);
            }
        }

        __syncthreads();
        if (kc + 2 < NK) fill(kc + 2, (kc + 2) % 3);
        else CP_COMMIT();
    }

    {
        int mrow = wid * 16 + (lane >> 2);
        int ncol = (lane & 3) * 2;
        #pragma unroll
        for (int nj = 0; nj < 4; nj++){
            int n = nj * 8 + ncol;
            *(float2*)&C[(size_t)(row0 + mrow) * 32 + n]     = make_float2(acc[nj][0], acc[nj][1]);
            *(float2*)&C[(size_t)(row0 + mrow + 8) * 32 + n] = make_float2(acc[nj][2], acc[nj][3]);
        }
    }
}

// ------------------------- prep (all weight packs, one launch) -------------------------
__device__ __forceinline__ void wsplit_job(int lb, int tid, const float* W,
                                           bf16* Wh, bf16* Wl, int Nsrc, int Ndst, int off)
{
    size_t i4 = (size_t)lb * 256 + tid;
    int nq = Nsrc / 4;
    int k  = (int)(i4 / nq);
    int c  = (int)(i4 % nq) * 4;
    float4 v = *(const float4*)(W + (size_t)k * Nsrc + c);
    bf16 hh[4], ll[4];
    splitf(v.x, hh[0], ll[0]); splitf(v.y, hh[1], ll[1]);
    splitf(v.z, hh[2], ll[2]); splitf(v.w, hh[3], ll[3]);
    size_t o = (size_t)k * Ndst + off + c;
    *(uint2*)(Wh + o) = *(uint2*)hh;
    *(uint2*)(Wl + o) = *(uint2*)ll;
}

__global__ void k_prep(const float* __restrict__ W_in, const float* __restrict__ W_D,
                       const float* __restrict__ W_cl, const float* __restrict__ fc1_w,
                       const float* __restrict__ W_out,
                       const float* __restrict__ fc2_w, const float* __restrict__ fc3_w,
                       const float* __restrict__ conv_w,
                       const float* __restrict__ b_in, const float* __restrict__ b_D,
                       const float* __restrict__ fc2_b, const float* __restrict__ fc3_b)
{
    int bid = blockIdx.x;
    int tid = threadIdx.x;
    if (bid < 1152){ wsplit_job(bid, tid, W_in, g_W15_h, g_W15_l, D2V, N2X, 0); return; }
    bid -= 1152;
    if (bid < 1152){ wsplit_job(bid, tid, W_D, g_W15_h, g_W15_l, D2V, N2X, D2V); return; }
    bid -= 1152;
    if (bid < 2304){ wsplit_job(bid, tid, W_cl, g_WclS_h, g_WclS_l, D2V, D2V, 0); return; }
    bid -= 2304;
    if (bid < 2304){ wsplit_job(bid, tid, fc1_w, g_f1_h, g_f1_l, D2V, D2V, 0); return; }
    bid -= 2304;
    if (bid < 1152){ wsplit_job(bid, tid, W_out, g_WoS_h, g_WoS_l, DMODEL, DMODEL, 0); return; }
    bid -= 1152;
    if (bid < 24){ wsplit_job(bid, tid, fc2_w, g_f23_h, g_f23_l, NSTATE, 32, 0); return; }
    bid -= 24;
    if (bid < 24){ wsplit_job(bid, tid, fc3_w, g_f23_h, g_f23_l, NSTATE, 32, NSTATE); return; }
    bid -= 24;
    if (bid < 4096){
        int o = bid >> 2;
        int i = (bid & 3) * 256 + tid;
        #pragma unroll
        for (int k = 0; k < 3; k++){
            float v = conv_w[(size_t)o * K3 + 3 * i + k];
            bf16 h, l; splitf(v, h, l);
            size_t off = (size_t)o * K3 + k * 1024 + i;
            g_cA_h[off] = h; g_cA_l[off] = l;
        }
        return;
    }
    bid -= 4096;
    if (bid < 12){
        int i = bid * 256 + tid;
        g_b15[i] = (i < D2V) ? b_in[i] : b_D[i - D2V];
        return;
    }
    bid -= 12;
    if (tid < 32) g_b23[tid] = (tid < NSTATE) ? fc2_b[tid] : fc3_b[tid - NSTATE];
}

// ------------------------- aux kernels -------------------------
__global__ void k_embed(const int* __restrict__ ids, const float* __restrict__ emb)
{
    int row = blockIdx.x;
    int id  = ids[row];
    const float* src = emb + (size_t)id * DMODEL;
    float s = 0.f, ss = 0.f;
    for (int d = threadIdx.x; d < DMODEL; d += blockDim.x){
        float v = __ldg(src + d);
        g_x[(size_t)row * DMODEL + d] = v;
        s += v; ss += v * v;
    }
    __shared__ float sh[64];
    int lane = threadIdx.x & 31, w = threadIdx.x >> 5;
    #pragma unroll
    for (int o = 16; o; o >>= 1){
        s  += __shfl_down_sync(0xffffffffu, s,  o);
        ss += __shfl_down_sync(0xffffffffu, ss, o);
    }
    if (!lane){ sh[w] = s; sh[32 + w] = ss; }
    __syncthreads();
    if (threadIdx.x == 0){
        float S = 0.f, SS = 0.f;
        int nw = blockDim.x >> 5;
        for (int i = 0; i < nw; i++){ S += sh[i]; SS += sh[32 + i]; }
        g_rowsum[row] = S; g_rowsq[row] = SS;
    }
}

__global__ void k_samplestats()
{
    int b = blockIdx.x;
    float s = 0.f, ss = 0.f;
    for (int r = threadIdx.x; r < LSEQ; r += blockDim.x){
        s += g_rowsum[b * LSEQ + r]; ss += g_rowsq[b * LSEQ + r];
    }
    __shared__ float sh[64];
    int lane = threadIdx.x & 31, w = threadIdx.x >> 5;
    #pragma unroll
    for (int o = 16; o; o >>= 1){
        s  += __shfl_down_sync(0xffffffffu, s,  o);
        ss += __shfl_down_sync(0xffffffffu, ss, o);
    }
    if (!lane){ sh[w] = s; sh[32 + w] = ss; }
    __syncthreads();
    if (threadIdx.x == 0){
        float S = 0.f, SS = 0.f;
        int nw = blockDim.x >> 5;
        for (int i = 0; i < nw; i++){ S += sh[i]; SS += sh[32 + i]; }
        float inv = 1.f / ((float)LSEQ * (float)DMODEL);
        float mu  = S * inv;
        float var = SS * inv - mu * mu;
        g_mu[b]   = mu;
        g_rsig[b] = rsqrtf(var + 1e-5f);
    }
}

__global__ void k_norm(const float* __restrict__ rms_w)
{
    int row = blockIdx.x;
    int b = row >> 10;
    float mu = g_mu[b], rs = g_rsig[b];
    float msq = rs * rs * (g_rowsq[row] - 2.f * mu * g_rowsum[row] + (float)DMODEL * mu * mu) / (float)DMODEL;
    float a = rs * rsqrtf(msq + 1e-5f);
    const float* xr = g_x + (size_t)row * DMODEL;
    for (int d = threadIdx.x; d < DMODEL; d += blockDim.x){
        float v = (xr[d] - mu) * a * rms_w[d];
        bf16 h, l; splitf(v, h, l);
        g_xnP_h[(size_t)row * DMODEL + d] = h;
        g_xnP_l[(size_t)row * DMODEL + d] = l;
    }
}

// merged conv B gather: one block per (b,i) row; stage row in smem (haloed), emit 3 shifted k-planes.
// NOTE: halo buffer stores are SCALAR (rowbuf+1 is not 16B-aligned — R10 crash).
__global__ void k_convB()
{
    __shared__ float rowbuf[D2V + 2];
    int i = blockIdx.x, b = blockIdx.y;
    int t4 = threadIdx.x * 4;
    const float* src = g_xpr + ((size_t)(b * LSEQ) + i) * N2X;
    float4 v = *(const float4*)(src + t4);
    rowbuf[1 + t4 + 0] = v.x;
    rowbuf[1 + t4 + 1] = v.y;
    rowbuf[1 + t4 + 2] = v.z;
    rowbuf[1 + t4 + 3] = v.w;
    if (threadIdx.x == 0){ rowbuf[0] = 0.f; rowbuf[D2V + 1] = 0.f; }
    __syncthreads();
    #pragma unroll
    for (int k = 0; k < 3; k++){
        bf16 hh[4], ll[4];
        #pragma unroll
        for (int j = 0; j < 4; j++) splitf(rowbuf[t4 + k + j], hh[j], ll[j]);
        size_t o = (size_t)b * K3 * D2V + (size_t)(k * 1024 + i) * D2V + t4;
        *(uint2*)(g_cB_h + o) = *(uint2*)hh;
        *(uint2*)(g_cB_l + o) = *(uint2*)ll;
    }
}

// s[row] = sum_n (Bm_n)(Cm_n), Bm/Cm = sum of KSPLIT partials + bias
__global__ void k_s()
{
    int row = blockIdx.x;
    int lane = threadIdx.x;
    float p = 0.f;
    if (lane < NSTATE){
        float bm = g_b23[lane], cm = g_b23[NSTATE + lane];
        #pragma unroll
        for (int ks = 0; ks < KSPLIT; ks++){
            bm += g_bc[((size_t)ks * ROWS + row) * 32 + lane];
            cm += g_bc[((size_t)ks * ROWS + row) * 32 + NSTATE + lane];
        }
        p = bm * cm;
    }
    #pragma unroll
    for (int o = 8; o; o >>= 1) p += __shfl_xor_sync(0xffffffffu, p, o);
    if (lane == 0) g_s[row] = p;
}

// prod = silu(xco*delta*s) * silu(xres_raw); split out
__global__ void k_prod()
{
    size_t i4 = (size_t)blockIdx.x * blockDim.x + threadIdx.x;
    int row = (int)(i4 / (D2V / 4));
    int c4  = (int)(i4 % (D2V / 4));
    float sv = g_s[row];
    float4 xo = ((const float4*)g_xco)[i4];
    float4 dl = ((const float4*)g_dl )[i4];
    float4 xr = *(const float4*)(g_xpr + (size_t)row * N2X + D2V + c4 * 4);
    float r0 = siluf(xo.x*dl.x*sv) * siluf(xr.x);
    float r1 = siluf(xo.y*dl.y*sv) * siluf(xr.y);
    float r2 = siluf(xo.z*dl.z*sv) * siluf(xr.z);
    float r3 = siluf(xo.w*dl.w*sv) * siluf(xr.w);
    bf16 hh[4], ll[4];
    splitf(r0, hh[0], ll[0]); splitf(r1, hh[1], ll[1]);
    splitf(r2, hh[2], ll[2]); splitf(r3, hh[3], ll[3]);
    *(uint2*)(g_prP_h + i4*4) = *(uint2*)hh;
    *(uint2*)(g_prP_l + i4*4) = *(uint2*)ll;
}

__global__ void k_maxpool(const float* __restrict__ out, float* __restrict__ pooled)
{
    int b = blockIdx.y;
    int d = blockIdx.x * blockDim.x + threadIdx.x;
    if (d >= DMODEL) return;
    const float* p = out + (size_t)b * LSEQ * DMODEL + d;
    float m = -FLT_MAX;
    for (int l = 0; l < LSEQ; l++) m = fmaxf(m, p[(size_t)l * DMODEL]);
    pooled[b * DMODEL + d] = m;
}

// ------------------------- launch -------------------------
extern "C" void kernel_launch(void* const* d_in, const int* in_sizes, int n_in,
                              void* d_out, int out_size)
{
    const int*   ids    = (const int*)  d_in[0];
    const float* emb    = (const float*)d_in[1];
    const float* rms_w  = (const float*)d_in[2];
    const float* W_in   = (const float*)d_in[3];
    const float* b_in   = (const float*)d_in[4];
    const float* conv_w = (const float*)d_in[5];
    const float* conv_b = (const float*)d_in[6];
    const float* W_cl   = (const float*)d_in[7];
    const float* b_cl   = (const float*)d_in[8];
    const float* fc1_w  = (const float*)d_in[9];
    const float* fc1_b  = (const float*)d_in[10];
    const float* fc2_w  = (const float*)d_in[11];
    const float* fc2_b  = (const float*)d_in[12];
    const float* fc3_w  = (const float*)d_in[13];
    const float* fc3_b  = (const float*)d_in[14];
    const float* W_D    = (const float*)d_in[16];
    const float* b_D    = (const float*)d_in[17];
    const float* W_out  = (const float*)d_in[18];
    const float* b_out  = (const float*)d_in[19];
    float* out = (float*)d_out;

    cudaFuncSetAttribute(k_tcW<0,false>, cudaFuncAttributeMaxDynamicSharedMemorySize, WSMEM);
    cudaFuncSetAttribute(k_tcW<0,true >, cudaFuncAttributeMaxDynamicSharedMemorySize, WSMEM);
    cudaFuncSetAttribute(k_tcW<1,true >, cudaFuncAttributeMaxDynamicSharedMemorySize, WSMEM);
    cudaFuncSetAttribute(k_tcW<2,false>, cudaFuncAttributeMaxDynamicSharedMemorySize, WSMEM);
    cudaFuncSetAttribute(k_tcN,          cudaFuncAttributeMaxDynamicSharedMemorySize, NSMEM);
    cudaFuncSetAttribute(k_tcS,          cudaFuncAttributeMaxDynamicSharedMemorySize, SSMEM);

    bf16 *xnh, *xnl, *xcah, *xcal, *xcoh, *xcol, *prh, *prl;
    bf16 *w15h, *w15l, *wclh, *wcll, *f1h, *f1l, *f23h, *f23l, *woh, *wol;
    bf16 *cah, *cal, *cbh, *cbl;
    float *pxpr, *pxco, *pdl, *pbc, *pb15;
    cudaGetSymbolAddress((void**)&xnh,  g_xnP_h);  cudaGetSymbolAddress((void**)&xnl,  g_xnP_l);
    cudaGetSymbolAddress((void**)&xcah, g_xcaP_h); cudaGetSymbolAddress((void**)&xcal, g_xcaP_l);
    cudaGetSymbolAddress((void**)&xcoh, g_xcoP_h); cudaGetSymbolAddress((void**)&xcol, g_xcoP_l);
    cudaGetSymbolAddress((void**)&prh,  g_prP_h);  cudaGetSymbolAddress((void**)&prl,  g_prP_l);
    cudaGetSymbolAddress((void**)&w15h, g_W15_h);  cudaGetSymbolAddress((void**)&w15l, g_W15_l);
    cudaGetSymbolAddress((void**)&wclh, g_WclS_h); cudaGetSymbolAddress((void**)&wcll, g_WclS_l);
    cudaGetSymbolAddress((void**)&f1h,  g_f1_h);   cudaGetSymbolAddress((void**)&f1l,  g_f1_l);
    cudaGetSymbolAddress((void**)&f23h, g_f23_h);  cudaGetSymbolAddress((void**)&f23l, g_f23_l);
    cudaGetSymbolAddress((void**)&woh,  g_WoS_h);  cudaGetSymbolAddress((void**)&wol,  g_WoS_l);
    cudaGetSymbolAddress((void**)&cah,  g_cA_h);   cudaGetSymbolAddress((void**)&cal,  g_cA_l);
    cudaGetSymbolAddress((void**)&cbh,  g_cB_h);   cudaGetSymbolAddress((void**)&cbl,  g_cB_l);
    cudaGetSymbolAddress((void**)&pxpr, g_xpr);
    cudaGetSymbolAddress((void**)&pxco, g_xco);
    cudaGetSymbolAddress((void**)&pdl,  g_dl);
    cudaGetSymbolAddress((void**)&pbc,  g_bc);
    cudaGetSymbolAddress((void**)&pb15, g_b15);

    // prep (weights/biases)
    k_prep<<<12221, 256>>>(W_in, W_D, W_cl, fc1_w, W_out, fc2_w, fc3_w, conv_w,
                           b_in, b_D, fc2_b, fc3_b);
    // embed + norms
    k_embed<<<ROWS, 256>>>(ids, emb);
    k_samplestats<<<BATCH, 256>>>();
    k_norm<<<ROWS, 256>>>(rms_w);

    // GEMM1+5: [xp | xres] = xn @ [W_in | W_D] + b  (fp32)
    k_tcW<0,false><<<dim3(N2X/256, ROWS/128, 1), 256, WSMEM>>>(
        xnh, xnl, w15h, w15l, pb15, nullptr, pxpr, nullptr, nullptr,
        DMODEL, N2X, 0, 0, 0);

    // conv operand gather (merged: 1 read, 3 shifted writes)
    k_convB<<<dim3(LSEQ, BATCH), 384>>>();

    // conv GEMM: xca = silu(cA @ cB + conv_b[row]), split out
    k_tcW<1,true><<<dim3(D2V/256, LSEQ/128, BATCH), 256, WSMEM>>>(
        cah, cal, cbh, cbl, nullptr, conv_b, nullptr, xcah, xcal,
        K3, D2V, 0, (long)K3*D2V, (long)LSEQ*D2V);

    // GEMM3: xco = xca @ W_cl + b_cl (fp32 + split)
    k_tcW<0,true><<<dim3(D2V/256, ROWS/128, 1), 256, WSMEM>>>(
        xcah, xcal, wclh, wcll, b_cl, nullptr, pxco, xcoh, xcol,
        D2V, D2V, 0, 0, 0);

    // side GEMM (K-split 4): Bm/Cm partials
    k_tcS<<<dim3(KSPLIT, ROWS/128), 256, SSMEM>>>(xcoh, xcol, f23h, f23l, pbc, D2V);

    // s[row]
    k_s<<<ROWS, 32>>>();

    // GEMM4: delta = softplus(xco @ fc1 + b1)  (fp32, N=1536 -> 3 waves)
    k_tcW<2,false><<<dim3(D2V/256, ROWS/128, 1), 256, WSMEM>>>(
        xcoh, xcol, f1h, f1l, fc1_b, nullptr, pdl, nullptr, nullptr,
        D2V, D2V, 0, 0, 0);

    // prod (split for GEMM6)
    k_prod<<<(ROWS * D2V / 4) / 256, 256>>>();

    // GEMM6: out = prod @ W_out + b_out
    k_tcN<<<dim3(DMODEL/BN, ROWS/BM, 1), 256, NSMEM>>>(
        prh, prl, woh, wol, b_out, out, D2V, DMODEL);

    if (out_size >= ROWS * DMODEL + BATCH * DMODEL)
        k_maxpool<<<dim3((DMODEL + 255) / 256, BATCH), 256>>>(out, out + (size_t)ROWS * DMODEL);
}

// round 12
// speedup vs baseline: 1.0596x; 1.0016x over previous
#include <cuda_runtime.h>
#include <cuda_bf16.h>
#include <math.h>
#include <float.h>
#include <stdint.h>

#define BATCH 8
#define LSEQ 1024
#define DMODEL 768
#define D2V 1536
#define N2X 3072
#define NSTATE 16
#define ROWS (BATCH*LSEQ)
#define K3 (3*LSEQ)

#define BM 128
#define BN 128
#define NSTAGES 3
#define NSTAGE_BYTES 65536u
#define NSMEM (NSTAGES*NSTAGE_BYTES)

#define WSTAGE 98304u
#define WOFF_AL 16384u
#define WOFF_BH 32768u
#define WOFF_BL 65536u
#define WSMEM (2u*WSTAGE)

#define SSTAGE 40960u
#define SOFF_AL 16384u
#define SOFF_BH 32768u
#define SOFF_BL 36864u
#define SSMEM (3u*SSTAGE)
#define KSPLIT 4

typedef __nv_bfloat16 bf16;

// ------------------------- device scratch -------------------------
__device__ float g_x   [ROWS*DMODEL];
__device__ float g_xpr [(size_t)ROWS*N2X];   // [xp | xres_raw] fp32
__device__ float g_bc  [(size_t)KSPLIT*ROWS*32];
__device__ float g_rowsum[ROWS];
__device__ float g_rowsq [ROWS];
__device__ float g_mu  [BATCH];
__device__ float g_rsig[BATCH];
__device__ float g_s   [ROWS];
__device__ float g_b15 [N2X];
__device__ float g_b23 [32];

__device__ bf16 g_xnP_h [ROWS*DMODEL], g_xnP_l [ROWS*DMODEL];
__device__ bf16 g_xcaP_h[ROWS*D2V],    g_xcaP_l[ROWS*D2V];
__device__ bf16 g_xcoP_h[ROWS*D2V],    g_xcoP_l[ROWS*D2V];
__device__ bf16 g_prP_h [ROWS*D2V],    g_prP_l [ROWS*D2V];
__device__ bf16 g_W15_h [DMODEL*N2X],  g_W15_l [DMODEL*N2X];
__device__ bf16 g_WclS_h[D2V*D2V],     g_WclS_l[D2V*D2V];
__device__ bf16 g_f1_h  [D2V*D2V],     g_f1_l  [D2V*D2V];
__device__ bf16 g_f23_h [D2V*32],      g_f23_l [D2V*32];
__device__ bf16 g_WoS_h [D2V*DMODEL],  g_WoS_l [D2V*DMODEL];
__device__ bf16 g_cA_h  [LSEQ*K3],     g_cA_l  [LSEQ*K3];
__device__ bf16 g_cB_h  [(size_t)BATCH*K3*D2V];
__device__ bf16 g_cB_l  [(size_t)BATCH*K3*D2V];

// ------------------------- helpers -------------------------
__device__ __forceinline__ float siluf(float v){ return __fdividef(v, 1.f + __expf(-v)); }
__device__ __forceinline__ float softplusf(float v){ return (v > 15.f) ? v : log1pf(__expf(v)); }

__device__ __forceinline__ uint32_t smem_u32(const void* p){
    uint32_t a;
    asm("{ .reg .u64 t; cvta.to.shared.u64 t, %1; cvt.u32.u64 %0, t; }" : "=r"(a) : "l"(p));
    return a;
}
__device__ __forceinline__ void cpa16(uint32_t dst, const void* src){
    asm volatile("cp.async.cg.shared.global [%0], [%1], 16;" :: "r"(dst), "l"(src) : "memory");
}
#define CP_COMMIT() asm volatile("cp.async.commit_group;" ::: "memory")
#define CP_WAIT(n)  asm volatile("cp.async.wait_group %0;" :: "n"(n) : "memory")

__device__ __forceinline__ void ldsm4(uint32_t addr, uint32_t* r){
    asm volatile("ldmatrix.sync.aligned.m8n8.x4.shared.b16 {%0,%1,%2,%3}, [%4];"
        : "=r"(r[0]), "=r"(r[1]), "=r"(r[2]), "=r"(r[3]) : "r"(addr));
}
__device__ __forceinline__ void ldsm4t(uint32_t addr, uint32_t* r0, uint32_t* r1){
    asm volatile("ldmatrix.sync.aligned.m8n8.x4.trans.shared.b16 {%0,%1,%2,%3}, [%4];"
        : "=r"(r0[0]), "=r"(r0[1]), "=r"(r1[0]), "=r"(r1[1]) : "r"(addr));
}
__device__ __forceinline__ void mma16816(float* d, const uint32_t* a, const uint32_t* b){
    asm volatile("mma.sync.aligned.m16n8k16.row.col.f32.bf16.bf16.f32 "
        "{%0,%1,%2,%3}, {%4,%5,%6,%7}, {%8,%9}, {%0,%1,%2,%3};"
        : "+f"(d[0]), "+f"(d[1]), "+f"(d[2]), "+f"(d[3])
        : "r"(a[0]), "r"(a[1]), "r"(a[2]), "r"(a[3]), "r"(b[0]), "r"(b[1]));
}
__device__ __forceinline__ void splitf(float v, bf16& h, bf16& l){
    h = __float2bfloat16(v);
    l = __float2bfloat16(v - __bfloat162float(h));
}

// ------------------------- WIDE HMMA GEMM 128x256 -------------------------
// EPI: 0 plain (+biasN), 1 silu(+biasM), 5 = GEMM4 fused prod epilogue.
// Writes fp32 C if C!=null; split Ch/Cl if SPLIT (EPI5 writes split itself).
template<int EPI, bool SPLIT>
__global__ void __launch_bounds__(256, 1) k_tcW(
    const bf16* __restrict__ Ah, const bf16* __restrict__ Al,
    const bf16* __restrict__ Bh, const bf16* __restrict__ Bl,
    const float* __restrict__ biasN, const float* __restrict__ biasM,
    float* __restrict__ C, bf16* __restrict__ Ch, bf16* __restrict__ Cl,
    const bf16* __restrict__ Xh, const bf16* __restrict__ Xl,
    const float* __restrict__ Xf, const float* __restrict__ Sv,
    int K, int N, long sA, long sB, long sC)
{
    extern __shared__ char smem[];
    const int tid  = threadIdx.x;
    const int wid  = tid >> 5, lane = tid & 31;
    const int wm   = wid & 1,  wn = wid >> 1;
    const int row0 = blockIdx.y * 128;
    const int col0 = blockIdx.x * 256;
    Ah += (size_t)blockIdx.z * sA;  Al += (size_t)blockIdx.z * sA;
    Bh += (size_t)blockIdx.z * sB;  Bl += (size_t)blockIdx.z * sB;
    if (C) C += (size_t)blockIdx.z * sC;
    if (SPLIT){ Ch += (size_t)blockIdx.z * sC; Cl += (size_t)blockIdx.z * sC; }
    const int NK = K >> 6;
    const uint32_t sbase = smem_u32(smem);

    float acc[4][8][4];
    #pragma unroll
    for (int mi = 0; mi < 4; mi++)
        #pragma unroll
        for (int nj = 0; nj < 8; nj++)
            #pragma unroll
            for (int q = 0; q < 4; q++) acc[mi][nj][q] = 0.f;

    auto fill = [&](int kc, int s){
        uint32_t st = sbase + (uint32_t)s * WSTAGE;
        const bf16* ap[2] = { Ah, Al };
        #pragma unroll
        for (int arr = 0; arr < 2; arr++){
            uint32_t base = st + arr * WOFF_AL;
            #pragma unroll
            for (int it = 0; it < 4; it++){
                int id = tid + it * 256;
                int r = id >> 3, u = id & 7;
                cpa16(base + r * 128 + (((uint32_t)(u ^ (r & 7))) << 4),
                      ap[arr] + (size_t)(row0 + r) * K + kc * 64 + u * 8);
            }
        }
        const bf16* bp[2] = { Bh, Bl };
        #pragma unroll
        for (int arr = 0; arr < 2; arr++){
            uint32_t base = st + WOFF_BH + arr * (WOFF_BL - WOFF_BH);
            #pragma unroll
            for (int it = 0; it < 8; it++){
                int id = tid + it * 256;
                int k = id >> 5, u = id & 31;
                cpa16(base + k * 512 + (((uint32_t)(u ^ (k & 7))) << 4),
                      bp[arr] + (size_t)(kc * 64 + k) * N + col0 + u * 8);
            }
        }
        CP_COMMIT();
    };

    fill(0, 0);
    fill(1, 1);

    for (int kc = 0; kc < NK; kc++){
        int s = kc & 1;
        CP_WAIT(1);
        __syncthreads();

        uint32_t aAh = sbase + (uint32_t)s * WSTAGE;
        uint32_t aAl = aAh + WOFF_AL;
        uint32_t aBh = aAh + WOFF_BH;
        uint32_t aBl = aAh + WOFF_BL;

        #pragma unroll
        for (int ks = 0; ks < 4; ks++){
            uint32_t ah[4][4], al[4][4];
            const int au = 2 * ks + (lane >> 4);
            #pragma unroll
            for (int mi = 0; mi < 4; mi++){
                int r = wm * 64 + mi * 16 + (lane & 15);
                uint32_t off = r * 128 + (((uint32_t)(au ^ (r & 7))) << 4);
                ldsm4(aAh + off, ah[mi]);
                ldsm4(aAl + off, al[mi]);
            }
            const int bk = ks * 16 + (lane & 15);
            #pragma unroll
            for (int p = 0; p < 4; p++){
                int u = wn * 8 + p * 2 + (lane >> 4);
                uint32_t off = bk * 512 + (((uint32_t)(u ^ (bk & 7))) << 4);
                uint32_t b0[2], b1[2];
                ldsm4t(aBh + off, b0, b1);
                #pragma unroll
                for (int mi = 0; mi < 4; mi++){
                    mma16816(acc[mi][2*p],   ah[mi], b0);
                    mma16816(acc[mi][2*p+1], ah[mi], b1);
                }
                #pragma unroll
                for (int mi = 0; mi < 4; mi++){
                    mma16816(acc[mi][2*p],   al[mi], b0);
                    mma16816(acc[mi][2*p+1], al[mi], b1);
                }
            }
            #pragma unroll
            for (int p = 0; p < 4; p++){
                int u = wn * 8 + p * 2 + (lane >> 4);
                uint32_t off = bk * 512 + (((uint32_t)(u ^ (bk & 7))) << 4);
                uint32_t b0[2], b1[2];
                ldsm4t(aBl + off, b0, b1);
                #pragma unroll
                for (int mi = 0; mi < 4; mi++){
                    mma16816(acc[mi][2*p],   ah[mi], b0);
                    mma16816(acc[mi][2*p+1], ah[mi], b1);
                }
            }
        }

        __syncthreads();
        if (kc + 2 < NK) fill(kc + 2, s);
        else CP_COMMIT();
    }

    CP_WAIT(0);
    __syncthreads();

    float* sf = (float*)smem;
    {
        const int rlo = lane >> 2;
        const int ncl = (lane & 3) * 2;
        #pragma unroll
        for (int mi = 0; mi < 4; mi++)
            #pragma unroll
            for (int nj = 0; nj < 8; nj++){
                int m = wm * 64 + mi * 16 + rlo;
                int n = wn * 64 + nj * 8 + ncl;
                *(float2*)&sf[(size_t)m * 260 + n]       = make_float2(acc[mi][nj][0], acc[mi][nj][1]);
                *(float2*)&sf[(size_t)(m + 8) * 260 + n] = make_float2(acc[mi][nj][2], acc[mi][nj][3]);
            }
    }
    __syncthreads();

    for (int i = tid; i < 128 * 64; i += 256){
        int r = i >> 6, c = (i & 63) * 4;
        int row = row0 + r;
        int col = col0 + c;
        float4 v4 = *(float4*)&sf[(size_t)r * 260 + c];
        float vv[4] = { v4.x, v4.y, v4.z, v4.w };

        if (EPI == 5){
            float sv = __ldg(Sv + row);
            size_t o = (size_t)row * N + col;
            uint2 xh2 = __ldg((const uint2*)(Xh + o));
            uint2 xl2 = __ldg((const uint2*)(Xl + o));
            float4 xr4 = __ldg((const float4*)(Xf + (size_t)row * N2X + D2V + col));
            const bf16* xhp = (const bf16*)&xh2;
            const bf16* xlp = (const bf16*)&xl2;
            const float* xrp = (const float*)&xr4;
            bf16 hh[4], ll[4];
            #pragma unroll
            for (int j = 0; j < 4; j++){
                float delta = softplusf(vv[j] + __ldg(biasN + col + j));
                float xco = __bfloat162float(xhp[j]) + __bfloat162float(xlp[j]);
                float pr = siluf(xco * delta * sv) * siluf(xrp[j]);
                splitf(pr, hh[j], ll[j]);
            }
            *(uint2*)(Ch + o) = *(uint2*)hh;
            *(uint2*)(Cl + o) = *(uint2*)ll;
        } else {
            float bm = biasM ? __ldg(biasM + row) : 0.f;
            #pragma unroll
            for (int j = 0; j < 4; j++){
                float t = vv[j] + bm + (biasN ? __ldg(biasN + col + j) : 0.f);
                if (EPI == 1) t = siluf(t);
                vv[j] = t;
            }
            size_t o = (size_t)row * N + col;
            if (C) *(float4*)(C + o) = make_float4(vv[0], vv[1], vv[2], vv[3]);
            if (SPLIT){
                bf16 hh[4], ll[4];
                #pragma unroll
                for (int j = 0; j < 4; j++) splitf(vv[j], hh[j], ll[j]);
                *(uint2*)(Ch + o) = *(uint2*)hh;
                *(uint2*)(Cl + o) = *(uint2*)ll;
            }
        }
    }
}

// ------------------------- NARROW HMMA GEMM 128x128 (GEMM6) ----
__global__ void __launch_bounds__(256, 1) k_tcN(
    const bf16* __restrict__ Ah, const bf16* __restrict__ Al,
    const bf16* __restrict__ Bh, const bf16* __restrict__ Bl,
    const float* __restrict__ biasN,
    float* __restrict__ C, int K, int N)
{
    extern __shared__ char smem[];
    const int tid  = threadIdx.x;
    const int wid  = tid >> 5, lane = tid & 31;
    const int wm   = wid & 3,  wn = wid >> 2;
    const int row0 = blockIdx.y * BM;
    const int col0 = blockIdx.x * BN;
    const int NK = K >> 6;
    const uint32_t sbase = smem_u32(smem);

    float acc[2][8][4];
    #pragma unroll
    for (int mi = 0; mi < 2; mi++)
        #pragma unroll
        for (int nj = 0; nj < 8; nj++)
            #pragma unroll
            for (int q = 0; q < 4; q++) acc[mi][nj][q] = 0.f;

    auto fill = [&](int kc, int s){
        uint32_t st = sbase + (uint32_t)s * NSTAGE_BYTES;
        const bf16* ap[2] = { Ah, Al };
        #pragma unroll
        for (int arr = 0; arr < 2; arr++){
            uint32_t base = st + arr * 16384u;
            #pragma unroll
            for (int it = 0; it < 4; it++){
                int id = tid + it * 256;
                int r = id >> 3, u = id & 7;
                cpa16(base + r * 128 + (((uint32_t)(u ^ (r & 7))) << 4),
                      ap[arr] + (size_t)(row0 + r) * K + kc * 64 + u * 8);
            }
        }
        const bf16* bp[2] = { Bh, Bl };
        #pragma unroll
        for (int arr = 0; arr < 2; arr++){
            uint32_t base = st + 32768u + arr * 16384u;
            #pragma unroll
            for (int it = 0; it < 4; it++){
                int id = tid + it * 256;
                int k = id >> 4, u = id & 15;
                cpa16(base + k * 256 + (((uint32_t)(u ^ (k & 7))) << 4),
                      bp[arr] + (size_t)(kc * 64 + k) * N + col0 + u * 8);
            }
        }
        CP_COMMIT();
    };

    fill(0, 0);
    if (NK > 1) fill(1, 1); else CP_COMMIT();

    for (int kc = 0; kc < NK; kc++){
        int s = kc % NSTAGES;
        CP_WAIT(1);
        __syncthreads();

        uint32_t aAh = sbase + (uint32_t)s * NSTAGE_BYTES;
        uint32_t aAl = aAh + 16384u;
        uint32_t aBh = aAh + 32768u;
        uint32_t aBl = aAh + 49152u;

        #pragma unroll
        for (int ks = 0; ks < 4; ks++){
            uint32_t ah[2][4], al[2][4], bb[8][2];
            const int arow = wm * 32 + (lane & 15);
            const int au   = 2 * ks + (lane >> 4);
            #pragma unroll
            for (int mi = 0; mi < 2; mi++){
                int r = arow + mi * 16;
                uint32_t off = r * 128 + (((uint32_t)(au ^ (r & 7))) << 4);
                ldsm4(aAh + off, ah[mi]);
                ldsm4(aAl + off, al[mi]);
            }
            const int bk = ks * 16 + (lane & 15);
            #pragma unroll
            for (int p = 0; p < 4; p++){
                int u = wn * 8 + p * 2 + (lane >> 4);
                uint32_t off = bk * 256 + (((uint32_t)(u ^ (bk & 7))) << 4);
                ldsm4t(aBh + off, bb[2*p], bb[2*p+1]);
            }
            #pragma unroll
            for (int mi = 0; mi < 2; mi++)
                #pragma unroll
                for (int nj = 0; nj < 8; nj++)
                    mma16816(acc[mi][nj], ah[mi], bb[nj]);
            #pragma unroll
            for (int mi = 0; mi < 2; mi++)
                #pragma unroll
                for (int nj = 0; nj < 8; nj++)
                    mma16816(acc[mi][nj], al[mi], bb[nj]);
            #pragma unroll
            for (int p = 0; p < 4; p++){
                int u = wn * 8 + p * 2 + (lane >> 4);
                uint32_t off = bk * 256 + (((uint32_t)(u ^ (bk & 7))) << 4);
                ldsm4t(aBl + off, bb[2*p], bb[2*p+1]);
            }
            #pragma unroll
            for (int mi = 0; mi < 2; mi++)
                #pragma unroll
                for (int nj = 0; nj < 8; nj++)
                    mma16816(acc[mi][nj], ah[mi], bb[nj]);
        }

        if (kc + 2 < NK) fill(kc + 2, (kc + 2) % NSTAGES);
        else CP_COMMIT();
    }

    __syncthreads();
    float* sf = (float*)smem;
    {
        const int mrow = wm * 32 + (lane >> 2);
        const int ncol = wn * 64 + (lane & 3) * 2;
        #pragma unroll
        for (int mi = 0; mi < 2; mi++)
            #pragma unroll
            for (int nj = 0; nj < 8; nj++){
                int m = mrow + mi * 16, n = ncol + nj * 8;
                *(float2*)&sf[(size_t)m * 132 + n]       = make_float2(acc[mi][nj][0], acc[mi][nj][1]);
                *(float2*)&sf[(size_t)(m + 8) * 132 + n] = make_float2(acc[mi][nj][2], acc[mi][nj][3]);
            }
    }
    __syncthreads();

    for (int i = tid; i < BM * (BN / 4); i += 256){
        int r = i >> 5, c = (i & 31) * 4;
        float4 v = *(float4*)&sf[(size_t)r * 132 + c];
        float vv[4] = { v.x, v.y, v.z, v.w };
        #pragma unroll
        for (int j = 0; j < 4; j++)
            vv[j] += __ldg(biasN + col0 + c + j);
        *(float4*)(C + (size_t)(row0 + r) * N + col0 + c) = make_float4(vv[0], vv[1], vv[2], vv[3]);
    }
}

// ------------------------- SIDE GEMM 128x32 K-split (Bm|Cm partials) ----------
__global__ void __launch_bounds__(256, 1) k_tcS(
    const bf16* __restrict__ Ah, const bf16* __restrict__ Al,
    const bf16* __restrict__ Bh, const bf16* __restrict__ Bl,
    float* __restrict__ C, int K)
{
    extern __shared__ char smem[];
    const int tid = threadIdx.x;
    const int wid = tid >> 5, lane = tid & 31;
    const int row0 = blockIdx.y * 128;
    const int kc0 = blockIdx.x * (K / KSPLIT / 64);
    const int NK = K / KSPLIT / 64;
    const uint32_t sbase = smem_u32(smem);
    C += (size_t)blockIdx.x * ROWS * 32;

    float acc[4][4];
    #pragma unroll
    for (int nj = 0; nj < 4; nj++)
        #pragma unroll
        for (int q = 0; q < 4; q++) acc[nj][q] = 0.f;

    auto fill = [&](int kc, int s){
        uint32_t st = sbase + (uint32_t)s * SSTAGE;
        const bf16* ap[2] = { Ah, Al };
        #pragma unroll
        for (int arr = 0; arr < 2; arr++){
            uint32_t base = st + arr * SOFF_AL;
            #pragma unroll
            for (int it = 0; it < 4; it++){
                int id = tid + it * 256;
                int r = id >> 3, u = id & 7;
                cpa16(base + r * 128 + (((uint32_t)(u ^ (r & 7))) << 4),
                      ap[arr] + (size_t)(row0 + r) * K + (kc0 + kc) * 64 + u * 8);
            }
        }
        const bf16* bp[2] = { Bh, Bl };
        #pragma unroll
        for (int arr = 0; arr < 2; arr++){
            uint32_t base = st + SOFF_BH + arr * (SOFF_BL - SOFF_BH);
            int k = tid >> 2, u = tid & 3;
            cpa16(base + k * 64 + (((uint32_t)(u ^ (k & 3))) << 4),
                  bp[arr] + (size_t)((kc0 + kc) * 64 + k) * 32 + u * 8);
        }
        CP_COMMIT();
    };

    fill(0, 0);
    fill(1, 1);

    for (int kc = 0; kc < NK; kc++){
        int s = kc % 3;
        CP_WAIT(1);
        __syncthreads();

        uint32_t aAh = sbase + (uint32_t)s * SSTAGE;
        uint32_t aAl = aAh + SOFF_AL;
        uint32_t aBh = aAh + SOFF_BH;
        uint32_t aBl = aAh + SOFF_BL;

        #pragma unroll
        for (int ks = 0; ks < 4; ks++){
            uint32_t ah[4], al[4], bh[4][2], bl[4][2];
            const int r = wid * 16 + (lane & 15);
            const int au = 2 * ks + (lane >> 4);
            uint32_t offA = r * 128 + (((uint32_t)(au ^ (r & 7))) << 4);
            ldsm4(aAh + offA, ah);
            ldsm4(aAl + offA, al);
            const int bk = ks * 16 + (lane & 15);
            #pragma unroll
            for (int p = 0; p < 2; p++){
                int u = p * 2 + (lane >> 4);
                uint32_t off = bk * 64 + (((uint32_t)(u ^ (bk & 3))) << 4);
                ldsm4t(aBh + off, bh[2*p], bh[2*p+1]);
                ldsm4t(aBl + off, bl[2*p], bl[2*p+1]);
            }
            #pragma unroll
            for (int nj = 0; nj < 4; nj++){
                mma16816(acc[nj], ah, bh[nj]);
                mma16816(acc[nj], al, bh[nj]);
                mma16816(acc[nj], ah, bl[nj]);
            }
        }

        __syncthreads();
        if (kc + 2 < NK) fill(kc + 2, (kc + 2) % 3);
        else CP_COMMIT();
    }

    {
        int mrow = wid * 16 + (lane >> 2);
        int ncol = (lane & 3) * 2;
        #pragma unroll
        for (int nj = 0; nj < 4; nj++){
            int n = nj * 8 + ncol;
            *(float2*)&C[(size_t)(row0 + mrow) * 32 + n]     = make_float2(acc[nj][0], acc[nj][1]);
            *(float2*)&C[(size_t)(row0 + mrow + 8) * 32 + n] = make_float2(acc[nj][2], acc[nj][3]);
        }
    }
}

// ------------------------- prep: embed + all weight packs, one launch -------------------------
__device__ __forceinline__ void wsplit_job(int lb, int tid, const float* W,
                                           bf16* Wh, bf16* Wl, int Nsrc, int Ndst, int off)
{
    size_t i4 = (size_t)lb * 256 + tid;
    int nq = Nsrc / 4;
    int k  = (int)(i4 / nq);
    int c  = (int)(i4 % nq) * 4;
    float4 v = *(const float4*)(W + (size_t)k * Nsrc + c);
    bf16 hh[4], ll[4];
    splitf(v.x, hh[0], ll[0]); splitf(v.y, hh[1], ll[1]);
    splitf(v.z, hh[2], ll[2]); splitf(v.w, hh[3], ll[3]);
    size_t o = (size_t)k * Ndst + off + c;
    *(uint2*)(Wh + o) = *(uint2*)hh;
    *(uint2*)(Wl + o) = *(uint2*)ll;
}

__global__ void k_prep(const int* __restrict__ ids, const float* __restrict__ emb,
                       const float* __restrict__ W_in, const float* __restrict__ W_D,
                       const float* __restrict__ W_cl, const float* __restrict__ fc1_w,
                       const float* __restrict__ W_out,
                       const float* __restrict__ fc2_w, const float* __restrict__ fc3_w,
                       const float* __restrict__ conv_w,
                       const float* __restrict__ b_in, const float* __restrict__ b_D,
                       const float* __restrict__ fc2_b, const float* __restrict__ fc3_b)
{
    int bid = blockIdx.x;
    int tid = threadIdx.x;

    if (bid < ROWS){
        // embed job (scheduled first: feeds critical path)
        int row = bid;
        int id  = ids[row];
        const float* src = emb + (size_t)id * DMODEL;
        float s = 0.f, ss = 0.f;
        for (int d = tid; d < DMODEL; d += 256){
            float v = __ldg(src + d);
            g_x[(size_t)row * DMODEL + d] = v;
            s += v; ss += v * v;
        }
        __shared__ float sh[64];
        int lane = tid & 31, w = tid >> 5;
        #pragma unroll
        for (int o = 16; o; o >>= 1){
            s  += __shfl_down_sync(0xffffffffu, s,  o);
            ss += __shfl_down_sync(0xffffffffu, ss, o);
        }
        if (!lane){ sh[w] = s; sh[32 + w] = ss; }
        __syncthreads();
        if (tid == 0){
            float S = 0.f, SS = 0.f;
            for (int i = 0; i < 8; i++){ S += sh[i]; SS += sh[32 + i]; }
            g_rowsum[row] = S; g_rowsq[row] = SS;
        }
        return;
    }
    bid -= ROWS;
    if (bid < 1152){ wsplit_job(bid, tid, W_in, g_W15_h, g_W15_l, D2V, N2X, 0); return; }
    bid -= 1152;
    if (bid < 1152){ wsplit_job(bid, tid, W_D, g_W15_h, g_W15_l, D2V, N2X, D2V); return; }
    bid -= 1152;
    if (bid < 2304){ wsplit_job(bid, tid, W_cl, g_WclS_h, g_WclS_l, D2V, D2V, 0); return; }
    bid -= 2304;
    if (bid < 2304){ wsplit_job(bid, tid, fc1_w, g_f1_h, g_f1_l, D2V, D2V, 0); return; }
    bid -= 2304;
    if (bid < 1152){ wsplit_job(bid, tid, W_out, g_WoS_h, g_WoS_l, DMODEL, DMODEL, 0); return; }
    bid -= 1152;
    if (bid < 24){ wsplit_job(bid, tid, fc2_w, g_f23_h, g_f23_l, NSTATE, 32, 0); return; }
    bid -= 24;
    if (bid < 24){ wsplit_job(bid, tid, fc3_w, g_f23_h, g_f23_l, NSTATE, 32, NSTATE); return; }
    bid -= 24;
    if (bid < 4096){
        int o = bid >> 2;
        int i = (bid & 3) * 256 + tid;
        #pragma unroll
        for (int k = 0; k < 3; k++){
            float v = conv_w[(size_t)o * K3 + 3 * i + k];
            bf16 h, l; splitf(v, h, l);
            size_t off = (size_t)o * K3 + k * 1024 + i;
            g_cA_h[off] = h; g_cA_l[off] = l;
        }
        return;
    }
    bid -= 4096;
    if (bid < 12){
        int i = bid * 256 + tid;
        g_b15[i] = (i < D2V) ? b_in[i] : b_D[i - D2V];
        return;
    }
    bid -= 12;
    if (tid < 32) g_b23[tid] = (tid < NSTATE) ? fc2_b[tid] : fc3_b[tid - NSTATE];
}
#define PREP_BLOCKS (ROWS + 1152 + 1152 + 2304 + 2304 + 1152 + 24 + 24 + 4096 + 12 + 1)

// ------------------------- aux kernels -------------------------
__global__ void k_samplestats()
{
    int b = blockIdx.x;
    float s = 0.f, ss = 0.f;
    for (int r = threadIdx.x; r < LSEQ; r += blockDim.x){
        s += g_rowsum[b * LSEQ + r]; ss += g_rowsq[b * LSEQ + r];
    }
    __shared__ float sh[64];
    int lane = threadIdx.x & 31, w = threadIdx.x >> 5;
    #pragma unroll
    for (int o = 16; o; o >>= 1){
        s  += __shfl_down_sync(0xffffffffu, s,  o);
        ss += __shfl_down_sync(0xffffffffu, ss, o);
    }
    if (!lane){ sh[w] = s; sh[32 + w] = ss; }
    __syncthreads();
    if (threadIdx.x == 0){
        float S = 0.f, SS = 0.f;
        int nw = blockDim.x >> 5;
        for (int i = 0; i < nw; i++){ S += sh[i]; SS += sh[32 + i]; }
        float inv = 1.f / ((float)LSEQ * (float)DMODEL);
        float mu  = S * inv;
        float var = SS * inv - mu * mu;
        g_mu[b]   = mu;
        g_rsig[b] = rsqrtf(var + 1e-5f);
    }
}

__global__ void k_norm(const float* __restrict__ rms_w)
{
    int row = blockIdx.x;
    int b = row >> 10;
    float mu = g_mu[b], rs = g_rsig[b];
    float msq = rs * rs * (g_rowsq[row] - 2.f * mu * g_rowsum[row] + (float)DMODEL * mu * mu) / (float)DMODEL;
    float a = rs * rsqrtf(msq + 1e-5f);
    const float* xr = g_x + (size_t)row * DMODEL;
    for (int d = threadIdx.x; d < DMODEL; d += blockDim.x){
        float v = (xr[d] - mu) * a * rms_w[d];
        bf16 h, l; splitf(v, h, l);
        g_xnP_h[(size_t)row * DMODEL + d] = h;
        g_xnP_l[(size_t)row * DMODEL + d] = l;
    }
}

// merged conv B gather (scalar halo stores — alignment)
__global__ void k_convB()
{
    __shared__ float rowbuf[D2V + 2];
    int i = blockIdx.x, b = blockIdx.y;
    int t4 = threadIdx.x * 4;
    const float* src = g_xpr + ((size_t)(b * LSEQ) + i) * N2X;
    float4 v = *(const float4*)(src + t4);
    rowbuf[1 + t4 + 0] = v.x;
    rowbuf[1 + t4 + 1] = v.y;
    rowbuf[1 + t4 + 2] = v.z;
    rowbuf[1 + t4 + 3] = v.w;
    if (threadIdx.x == 0){ rowbuf[0] = 0.f; rowbuf[D2V + 1] = 0.f; }
    __syncthreads();
    #pragma unroll
    for (int k = 0; k < 3; k++){
        bf16 hh[4], ll[4];
        #pragma unroll
        for (int j = 0; j < 4; j++) splitf(rowbuf[t4 + k + j], hh[j], ll[j]);
        size_t o = (size_t)b * K3 * D2V + (size_t)(k * 1024 + i) * D2V + t4;
        *(uint2*)(g_cB_h + o) = *(uint2*)hh;
        *(uint2*)(g_cB_l + o) = *(uint2*)ll;
    }
}

__global__ void k_s()
{
    int row = blockIdx.x;
    int lane = threadIdx.x;
    float p = 0.f;
    if (lane < NSTATE){
        float bm = g_b23[lane], cm = g_b23[NSTATE + lane];
        #pragma unroll
        for (int ks = 0; ks < KSPLIT; ks++){
            bm += g_bc[((size_t)ks * ROWS + row) * 32 + lane];
            cm += g_bc[((size_t)ks * ROWS + row) * 32 + NSTATE + lane];
        }
        p = bm * cm;
    }
    #pragma unroll
    for (int o = 8; o; o >>= 1) p += __shfl_xor_sync(0xffffffffu, p, o);
    if (lane == 0) g_s[row] = p;
}

__global__ void k_maxpool(const float* __restrict__ out, float* __restrict__ pooled)
{
    int b = blockIdx.y;
    int d = blockIdx.x * blockDim.x + threadIdx.x;
    if (d >= DMODEL) return;
    const float* p = out + (size_t)b * LSEQ * DMODEL + d;
    float m = -FLT_MAX;
    for (int l = 0; l < LSEQ; l++) m = fmaxf(m, p[(size_t)l * DMODEL]);
    pooled[b * DMODEL + d] = m;
}

// ------------------------- launch -------------------------
extern "C" void kernel_launch(void* const* d_in, const int* in_sizes, int n_in,
                              void* d_out, int out_size)
{
    const int*   ids    = (const int*)  d_in[0];
    const float* emb    = (const float*)d_in[1];
    const float* rms_w  = (const float*)d_in[2];
    const float* W_in   = (const float*)d_in[3];
    const float* b_in   = (const float*)d_in[4];
    const float* conv_w = (const float*)d_in[5];
    const float* conv_b = (const float*)d_in[6];
    const float* W_cl   = (const float*)d_in[7];
    const float* b_cl   = (const float*)d_in[8];
    const float* fc1_w  = (const float*)d_in[9];
    const float* fc1_b  = (const float*)d_in[10];
    const float* fc2_w  = (const float*)d_in[11];
    const float* fc2_b  = (const float*)d_in[12];
    const float* fc3_w  = (const float*)d_in[13];
    const float* fc3_b  = (const float*)d_in[14];
    const float* W_D    = (const float*)d_in[16];
    const float* b_D    = (const float*)d_in[17];
    const float* W_out  = (const float*)d_in[18];
    const float* b_out  = (const float*)d_in[19];
    float* out = (float*)d_out;

    cudaFuncSetAttribute(k_tcW<0,false>, cudaFuncAttributeMaxDynamicSharedMemorySize, WSMEM);
    cudaFuncSetAttribute(k_tcW<0,true >, cudaFuncAttributeMaxDynamicSharedMemorySize, WSMEM);
    cudaFuncSetAttribute(k_tcW<1,true >, cudaFuncAttributeMaxDynamicSharedMemorySize, WSMEM);
    cudaFuncSetAttribute(k_tcW<5,true >, cudaFuncAttributeMaxDynamicSharedMemorySize, WSMEM);
    cudaFuncSetAttribute(k_tcN,          cudaFuncAttributeMaxDynamicSharedMemorySize, NSMEM);
    cudaFuncSetAttribute(k_tcS,          cudaFuncAttributeMaxDynamicSharedMemorySize, SSMEM);

    bf16 *xnh, *xnl, *xcah, *xcal, *xcoh, *xcol, *prh, *prl;
    bf16 *w15h, *w15l, *wclh, *wcll, *f1h, *f1l, *f23h, *f23l, *woh, *wol;
    bf16 *cah, *cal, *cbh, *cbl;
    float *pxpr, *pbc, *pb15, *ps;
    cudaGetSymbolAddress((void**)&xnh,  g_xnP_h);  cudaGetSymbolAddress((void**)&xnl,  g_xnP_l);
    cudaGetSymbolAddress((void**)&xcah, g_xcaP_h); cudaGetSymbolAddress((void**)&xcal, g_xcaP_l);
    cudaGetSymbolAddress((void**)&xcoh, g_xcoP_h); cudaGetSymbolAddress((void**)&xcol, g_xcoP_l);
    cudaGetSymbolAddress((void**)&prh,  g_prP_h);  cudaGetSymbolAddress((void**)&prl,  g_prP_l);
    cudaGetSymbolAddress((void**)&w15h, g_W15_h);  cudaGetSymbolAddress((void**)&w15l, g_W15_l);
    cudaGetSymbolAddress((void**)&wclh, g_WclS_h); cudaGetSymbolAddress((void**)&wcll, g_WclS_l);
    cudaGetSymbolAddress((void**)&f1h,  g_f1_h);   cudaGetSymbolAddress((void**)&f1l,  g_f1_l);
    cudaGetSymbolAddress((void**)&f23h, g_f23_h);  cudaGetSymbolAddress((void**)&f23l, g_f23_l);
    cudaGetSymbolAddress((void**)&woh,  g_WoS_h);  cudaGetSymbolAddress((void**)&wol,  g_WoS_l);
    cudaGetSymbolAddress((void**)&cah,  g_cA_h);   cudaGetSymbolAddress((void**)&cal,  g_cA_l);
    cudaGetSymbolAddress((void**)&cbh,  g_cB_h);   cudaGetSymbolAddress((void**)&cbl,  g_cB_l);
    cudaGetSymbolAddress((void**)&pxpr, g_xpr);
    cudaGetSymbolAddress((void**)&pbc,  g_bc);
    cudaGetSymbolAddress((void**)&pb15, g_b15);
    cudaGetSymbolAddress((void**)&ps,   g_s);

    // prep: embed + all weight/bias packs in one launch
    k_prep<<<PREP_BLOCKS, 256>>>(ids, emb, W_in, W_D, W_cl, fc1_w, W_out,
                                 fc2_w, fc3_w, conv_w, b_in, b_D, fc2_b, fc3_b);
    k_samplestats<<<BATCH, 256>>>();
    k_norm<<<ROWS, 256>>>(rms_w);

    // GEMM1+5: [xp | xres] = xn @ [W_in | W_D] + b  (fp32)
    k_tcW<0,false><<<dim3(N2X/256, ROWS/128, 1), 256, WSMEM>>>(
        xnh, xnl, w15h, w15l, pb15, nullptr, pxpr, nullptr, nullptr,
        nullptr, nullptr, nullptr, nullptr,
        DMODEL, N2X, 0, 0, 0);

    // conv operand gather
    k_convB<<<dim3(LSEQ, BATCH), 384>>>();

    // conv GEMM: xca = silu(cA @ cB + conv_b[row]), split out
    k_tcW<1,true><<<dim3(D2V/256, LSEQ/128, BATCH), 256, WSMEM>>>(
        cah, cal, cbh, cbl, nullptr, conv_b, nullptr, xcah, xcal,
        nullptr, nullptr, nullptr, nullptr,
        K3, D2V, 0, (long)K3*D2V, (long)LSEQ*D2V);

    // GEMM3: xco = xca @ W_cl + b_cl (split only)
    k_tcW<0,true><<<dim3(D2V/256, ROWS/128, 1), 256, WSMEM>>>(
        xcah, xcal, wclh, wcll, b_cl, nullptr, nullptr, xcoh, xcol,
        nullptr, nullptr, nullptr, nullptr,
        D2V, D2V, 0, 0, 0);

    // side GEMM (K-split 4): Bm/Cm partials
    k_tcS<<<dim3(KSPLIT, ROWS/128), 256, SSMEM>>>(xcoh, xcol, f23h, f23l, pbc, D2V);

    // s[row]
    k_s<<<ROWS, 32>>>();

    // GEMM4 (EPI5): prod split = silu(xco*softplus(xco@fc1+b1)*s) * silu(xres)
    k_tcW<5,true><<<dim3(D2V/256, ROWS/128, 1), 256, WSMEM>>>(
        xcoh, xcol, f1h, f1l, fc1_b, nullptr, nullptr, prh, prl,
        xcoh, xcol, pxpr, ps,
        D2V, D2V, 0, 0, 0);

    // GEMM6: out = prod @ W_out + b_out
    k_tcN<<<dim3(DMODEL/BN, ROWS/BM, 1), 256, NSMEM>>>(
        prh, prl, woh, wol, b_out, out, D2V, DMODEL);

    if (out_size >= ROWS * DMODEL + BATCH * DMODEL)
        k_maxpool<<<dim3((DMODEL + 255) / 256, BATCH), 256>>>(out, out + (size_t)ROWS * DMODEL);
}

// round 13
// speedup vs baseline: 1.0739x; 1.0135x over previous
#include <cuda_runtime.h>
#include <cuda_bf16.h>
#include <math.h>
#include <float.h>
#include <stdint.h>

#define BATCH 8
#define LSEQ 1024
#define DMODEL 768
#define D2V 1536
#define N2X 3072
#define NSTATE 16
#define ROWS (BATCH*LSEQ)
#define K3 (3*LSEQ)

#define BM 128
#define BN 128
#define NSTAGES 3
#define NSTAGE_BYTES 65536u
#define NSMEM (NSTAGES*NSTAGE_BYTES)

// wide kernel: A triple-buffer (3x32K), B double-buffer (2x64K) = 224KB
#define WA_BUF(i) ((uint32_t)(i)*32768u)
#define WB_BUF(i) (98304u + (uint32_t)(i)*65536u)
#define WSMEM 229376u

#define SSTAGE 40960u
#define SOFF_AL 16384u
#define SOFF_BH 32768u
#define SOFF_BL 36864u
#define SSMEM (3u*SSTAGE)
#define KSPLIT 4

typedef __nv_bfloat16 bf16;

// ------------------------- device scratch -------------------------
__device__ float g_x   [ROWS*DMODEL];
__device__ float g_xpr [(size_t)ROWS*N2X];
__device__ float g_bc  [(size_t)KSPLIT*ROWS*32];
__device__ float g_rowsum[ROWS];
__device__ float g_rowsq [ROWS];
__device__ float g_mu  [BATCH];
__device__ float g_rsig[BATCH];
__device__ float g_s   [ROWS];
__device__ float g_b15 [N2X];
__device__ float g_b23 [32];

__device__ bf16 g_xnP_h [ROWS*DMODEL], g_xnP_l [ROWS*DMODEL];
__device__ bf16 g_xcaP_h[ROWS*D2V],    g_xcaP_l[ROWS*D2V];
__device__ bf16 g_xcoP_h[ROWS*D2V],    g_xcoP_l[ROWS*D2V];
__device__ bf16 g_prP_h [ROWS*D2V],    g_prP_l [ROWS*D2V];
__device__ bf16 g_W15_h [DMODEL*N2X],  g_W15_l [DMODEL*N2X];
__device__ bf16 g_WclS_h[D2V*D2V],     g_WclS_l[D2V*D2V];
__device__ bf16 g_f1_h  [D2V*D2V],     g_f1_l  [D2V*D2V];
__device__ bf16 g_f23_h [D2V*32],      g_f23_l [D2V*32];
__device__ bf16 g_WoS_h [D2V*DMODEL],  g_WoS_l [D2V*DMODEL];
__device__ bf16 g_cA_h  [LSEQ*K3],     g_cA_l  [LSEQ*K3];
__device__ bf16 g_cB_h  [(size_t)BATCH*K3*D2V];
__device__ bf16 g_cB_l  [(size_t)BATCH*K3*D2V];

// ------------------------- helpers -------------------------
__device__ __forceinline__ float siluf(float v){ return __fdividef(v, 1.f + __expf(-v)); }
__device__ __forceinline__ float softplusf(float v){ return (v > 15.f) ? v : log1pf(__expf(v)); }

__device__ __forceinline__ uint32_t smem_u32(const void* p){
    uint32_t a;
    asm("{ .reg .u64 t; cvta.to.shared.u64 t, %1; cvt.u32.u64 %0, t; }" : "=r"(a) : "l"(p));
    return a;
}
__device__ __forceinline__ void cpa16(uint32_t dst, const void* src){
    asm volatile("cp.async.cg.shared.global [%0], [%1], 16;" :: "r"(dst), "l"(src) : "memory");
}
#define CP_COMMIT() asm volatile("cp.async.commit_group;" ::: "memory")
#define CP_WAIT(n)  asm volatile("cp.async.wait_group %0;" :: "n"(n) : "memory")

__device__ __forceinline__ void ldsm4(uint32_t addr, uint32_t* r){
    asm volatile("ldmatrix.sync.aligned.m8n8.x4.shared.b16 {%0,%1,%2,%3}, [%4];"
        : "=r"(r[0]), "=r"(r[1]), "=r"(r[2]), "=r"(r[3]) : "r"(addr));
}
__device__ __forceinline__ void ldsm4t(uint32_t addr, uint32_t* r0, uint32_t* r1){
    asm volatile("ldmatrix.sync.aligned.m8n8.x4.trans.shared.b16 {%0,%1,%2,%3}, [%4];"
        : "=r"(r0[0]), "=r"(r0[1]), "=r"(r1[0]), "=r"(r1[1]) : "r"(addr));
}
__device__ __forceinline__ void mma16816(float* d, const uint32_t* a, const uint32_t* b){
    asm volatile("mma.sync.aligned.m16n8k16.row.col.f32.bf16.bf16.f32 "
        "{%0,%1,%2,%3}, {%4,%5,%6,%7}, {%8,%9}, {%0,%1,%2,%3};"
        : "+f"(d[0]), "+f"(d[1]), "+f"(d[2]), "+f"(d[3])
        : "r"(a[0]), "r"(a[1]), "r"(a[2]), "r"(a[3]), "r"(b[0]), "r"(b[1]));
}
__device__ __forceinline__ void splitf(float v, bf16& h, bf16& l){
    h = __float2bfloat16(v);
    l = __float2bfloat16(v - __bfloat162float(h));
}

// ------------------------- WIDE HMMA GEMM 128x256, A x3 / B x2 pipeline ----------
// EPI: 0 plain fp32 (+biasN), 1 silu(+biasM) split, 5 = GEMM4 fused prod epilogue.
template<int EPI, bool SPLIT>
__global__ void __launch_bounds__(256, 1) k_tcW(
    const bf16* __restrict__ Ah, const bf16* __restrict__ Al,
    const bf16* __restrict__ Bh, const bf16* __restrict__ Bl,
    const float* __restrict__ biasN, const float* __restrict__ biasM,
    float* __restrict__ C, bf16* __restrict__ Ch, bf16* __restrict__ Cl,
    const bf16* __restrict__ Xh, const bf16* __restrict__ Xl,
    const float* __restrict__ Xf, const float* __restrict__ Sv,
    int K, int N, long sA, long sB, long sC)
{
    extern __shared__ char smem[];
    const int tid  = threadIdx.x;
    const int wid  = tid >> 5, lane = tid & 31;
    const int wm   = wid & 1,  wn = wid >> 1;
    const int row0 = blockIdx.y * 128;
    const int col0 = blockIdx.x * 256;
    Ah += (size_t)blockIdx.z * sA;  Al += (size_t)blockIdx.z * sA;
    Bh += (size_t)blockIdx.z * sB;  Bl += (size_t)blockIdx.z * sB;
    if (C) C += (size_t)blockIdx.z * sC;
    if (SPLIT){ Ch += (size_t)blockIdx.z * sC; Cl += (size_t)blockIdx.z * sC; }
    const int NK = K >> 6;
    const uint32_t sbase = smem_u32(smem);

    float acc[4][8][4];
    #pragma unroll
    for (int mi = 0; mi < 4; mi++)
        #pragma unroll
        for (int nj = 0; nj < 8; nj++)
            #pragma unroll
            for (int q = 0; q < 4; q++) acc[mi][nj][q] = 0.f;

    // A fill (all threads): 128x64 bf16 h+l into A buf (kc%3)
    auto fillA = [&](int kc){
        uint32_t base = sbase + WA_BUF(kc % 3);
        const bf16* ap[2] = { Ah, Al };
        #pragma unroll
        for (int arr = 0; arr < 2; arr++){
            uint32_t b2 = base + arr * 16384u;
            #pragma unroll
            for (int it = 0; it < 4; it++){
                int id = tid + it * 256;
                int r = id >> 3, u = id & 7;
                cpa16(b2 + r * 128 + (((uint32_t)(u ^ (r & 7))) << 4),
                      ap[arr] + (size_t)(row0 + r) * K + kc * 64 + u * 8);
            }
        }
    };
    // B fill (all threads, prologue only): 64x256 h+l into B buf (kc&1)
    auto fillBfull = [&](int kc){
        uint32_t base = sbase + WB_BUF(kc & 1);
        const bf16* bp[2] = { Bh, Bl };
        #pragma unroll
        for (int arr = 0; arr < 2; arr++){
            uint32_t b2 = base + arr * 32768u;
            #pragma unroll
            for (int it = 0; it < 8; it++){
                int id = tid + it * 256;
                int k = id >> 5, u = id & 31;
                cpa16(b2 + k * 512 + (((uint32_t)(u ^ (k & 7))) << 4),
                      bp[arr] + (size_t)(kc * 64 + k) * N + col0 + u * 8);
            }
        }
    };
    // B fill (pair-owned region): warp (wm,wn) fills rows wm*32..+32, units wn*8..+8
    auto fillBown = [&](int kc){
        uint32_t base = sbase + WB_BUF(kc & 1);
        const bf16* bp[2] = { Bh, Bl };
        #pragma unroll
        for (int arr = 0; arr < 2; arr++){
            uint32_t b2 = base + arr * 32768u;
            #pragma unroll
            for (int it = 0; it < 8; it++){
                int idx = lane + it * 32;           // 0..255
                int k = wm * 32 + (idx >> 3);       // own 32 rows
                int u = wn * 8 + (idx & 7);         // own 8 units (128B)
                cpa16(b2 + k * 512 + (((uint32_t)(u ^ (k & 7))) << 4),
                      bp[arr] + (size_t)(kc * 64 + k) * N + col0 + u * 8);
            }
        }
    };

    fillA(0); fillBfull(0); CP_COMMIT();
    fillA(1); fillBfull(1); CP_COMMIT();

    for (int kc = 0; kc < NK; kc++){
        CP_WAIT(1);
        __syncthreads();                       // stage kc fully arrived; all warps done with kc-1

        if (kc + 2 < NK) fillA(kc + 2);        // into A buf (kc+2)%3 — conflict-free, overlaps MMA

        uint32_t aAh = sbase + WA_BUF(kc % 3);
        uint32_t aAl = aAh + 16384u;
        uint32_t aBh = sbase + WB_BUF(kc & 1);
        uint32_t aBl = aBh + 32768u;

        #pragma unroll
        for (int ks = 0; ks < 4; ks++){
            uint32_t ah[4][4], al[4][4];
            const int au = 2 * ks + (lane >> 4);
            #pragma unroll
            for (int mi = 0; mi < 4; mi++){
                int r = wm * 64 + mi * 16 + (lane & 15);
                uint32_t off = r * 128 + (((uint32_t)(au ^ (r & 7))) << 4);
                ldsm4(aAh + off, ah[mi]);
                ldsm4(aAl + off, al[mi]);
            }
            const int bk = ks * 16 + (lane & 15);
            #pragma unroll
            for (int p = 0; p < 4; p++){
                int u = wn * 8 + p * 2 + (lane >> 4);
                uint32_t off = bk * 512 + (((uint32_t)(u ^ (bk & 7))) << 4);
                uint32_t b0[2], b1[2];
                ldsm4t(aBh + off, b0, b1);
                #pragma unroll
                for (int mi = 0; mi < 4; mi++){
                    mma16816(acc[mi][2*p],   ah[mi], b0);
                    mma16816(acc[mi][2*p+1], ah[mi], b1);
                }
                #pragma unroll
                for (int mi = 0; mi < 4; mi++){
                    mma16816(acc[mi][2*p],   al[mi], b0);
                    mma16816(acc[mi][2*p+1], al[mi], b1);
                }
            }
            #pragma unroll
            for (int p = 0; p < 4; p++){
                int u = wn * 8 + p * 2 + (lane >> 4);
                uint32_t off = bk * 512 + (((uint32_t)(u ^ (bk & 7))) << 4);
                uint32_t b0[2], b1[2];
                ldsm4t(aBl + off, b0, b1);
                #pragma unroll
                for (int mi = 0; mi < 4; mi++){
                    mma16816(acc[mi][2*p],   ah[mi], b0);
                    mma16816(acc[mi][2*p+1], ah[mi], b1);
                }
            }
        }

        // pair barrier: both warps of (wn) finished reading B(kc) -> self-fill own region
        asm volatile("bar.sync %0, 64;" :: "r"(1 + wn) : "memory");
        if (kc + 2 < NK) fillBown(kc + 2);
        CP_COMMIT();
    }

    CP_WAIT(0);
    __syncthreads();

    // ---- epilogue: acc -> smem (260-pitch) -> global
    float* sf = (float*)smem;
    {
        const int rlo = lane >> 2;
        const int ncl = (lane & 3) * 2;
        #pragma unroll
        for (int mi = 0; mi < 4; mi++)
            #pragma unroll
            for (int nj = 0; nj < 8; nj++){
                int m = wm * 64 + mi * 16 + rlo;
                int n = wn * 64 + nj * 8 + ncl;
                *(float2*)&sf[(size_t)m * 260 + n]       = make_float2(acc[mi][nj][0], acc[mi][nj][1]);
                *(float2*)&sf[(size_t)(m + 8) * 260 + n] = make_float2(acc[mi][nj][2], acc[mi][nj][3]);
            }
    }
    __syncthreads();

    for (int i = tid; i < 128 * 64; i += 256){
        int r = i >> 6, c = (i & 63) * 4;
        int row = row0 + r;
        int col = col0 + c;
        float4 v4 = *(float4*)&sf[(size_t)r * 260 + c];
        float vv[4] = { v4.x, v4.y, v4.z, v4.w };

        if (EPI == 5){
            float sv = __ldg(Sv + row);
            size_t o = (size_t)row * N + col;
            uint2 xh2 = __ldg((const uint2*)(Xh + o));
            uint2 xl2 = __ldg((const uint2*)(Xl + o));
            float4 xr4 = __ldg((const float4*)(Xf + (size_t)row * N2X + D2V + col));
            const bf16* xhp = (const bf16*)&xh2;
            const bf16* xlp = (const bf16*)&xl2;
            const float* xrp = (const float*)&xr4;
            bf16 hh[4], ll[4];
            #pragma unroll
            for (int j = 0; j < 4; j++){
                float delta = softplusf(vv[j] + __ldg(biasN + col + j));
                float xco = __bfloat162float(xhp[j]) + __bfloat162float(xlp[j]);
                float pr = siluf(xco * delta * sv) * siluf(xrp[j]);
                splitf(pr, hh[j], ll[j]);
            }
            *(uint2*)(Ch + o) = *(uint2*)hh;
            *(uint2*)(Cl + o) = *(uint2*)ll;
        } else {
            float bm = biasM ? __ldg(biasM + row) : 0.f;
            #pragma unroll
            for (int j = 0; j < 4; j++){
                float t = vv[j] + bm + (biasN ? __ldg(biasN + col + j) : 0.f);
                if (EPI == 1) t = siluf(t);
                vv[j] = t;
            }
            size_t o = (size_t)row * N + col;
            if (C) *(float4*)(C + o) = make_float4(vv[0], vv[1], vv[2], vv[3]);
            if (SPLIT){
                bf16 hh[4], ll[4];
                #pragma unroll
                for (int j = 0; j < 4; j++) splitf(vv[j], hh[j], ll[j]);
                *(uint2*)(Ch + o) = *(uint2*)hh;
                *(uint2*)(Cl + o) = *(uint2*)ll;
            }
        }
    }
}

// ------------------------- NARROW HMMA GEMM 128x128 (GEMM6) ----
__global__ void __launch_bounds__(256, 1) k_tcN(
    const bf16* __restrict__ Ah, const bf16* __restrict__ Al,
    const bf16* __restrict__ Bh, const bf16* __restrict__ Bl,
    const float* __restrict__ biasN,
    float* __restrict__ C, int K, int N)
{
    extern __shared__ char smem[];
    const int tid  = threadIdx.x;
    const int wid  = tid >> 5, lane = tid & 31;
    const int wm   = wid & 3,  wn = wid >> 2;
    const int row0 = blockIdx.y * BM;
    const int col0 = blockIdx.x * BN;
    const int NK = K >> 6;
    const uint32_t sbase = smem_u32(smem);

    float acc[2][8][4];
    #pragma unroll
    for (int mi = 0; mi < 2; mi++)
        #pragma unroll
        for (int nj = 0; nj < 8; nj++)
            #pragma unroll
            for (int q = 0; q < 4; q++) acc[mi][nj][q] = 0.f;

    auto fill = [&](int kc, int s){
        uint32_t st = sbase + (uint32_t)s * NSTAGE_BYTES;
        const bf16* ap[2] = { Ah, Al };
        #pragma unroll
        for (int arr = 0; arr < 2; arr++){
            uint32_t base = st + arr * 16384u;
            #pragma unroll
            for (int it = 0; it < 4; it++){
                int id = tid + it * 256;
                int r = id >> 3, u = id & 7;
                cpa16(base + r * 128 + (((uint32_t)(u ^ (r & 7))) << 4),
                      ap[arr] + (size_t)(row0 + r) * K + kc * 64 + u * 8);
            }
        }
        const bf16* bp[2] = { Bh, Bl };
        #pragma unroll
        for (int arr = 0; arr < 2; arr++){
            uint32_t base = st + 32768u + arr * 16384u;
            #pragma unroll
            for (int it = 0; it < 4; it++){
                int id = tid + it * 256;
                int k = id >> 4, u = id & 15;
                cpa16(base + k * 256 + (((uint32_t)(u ^ (k & 7))) << 4),
                      bp[arr] + (size_t)(kc * 64 + k) * N + col0 + u * 8);
            }
        }
        CP_COMMIT();
    };

    fill(0, 0);
    if (NK > 1) fill(1, 1); else CP_COMMIT();

    for (int kc = 0; kc < NK; kc++){
        int s = kc % NSTAGES;
        CP_WAIT(1);
        __syncthreads();

        uint32_t aAh = sbase + (uint32_t)s * NSTAGE_BYTES;
        uint32_t aAl = aAh + 16384u;
        uint32_t aBh = aAh + 32768u;
        uint32_t aBl = aAh + 49152u;

        #pragma unroll
        for (int ks = 0; ks < 4; ks++){
            uint32_t ah[2][4], al[2][4], bb[8][2];
            const int arow = wm * 32 + (lane & 15);
            const int au   = 2 * ks + (lane >> 4);
            #pragma unroll
            for (int mi = 0; mi < 2; mi++){
                int r = arow + mi * 16;
                uint32_t off = r * 128 + (((uint32_t)(au ^ (r & 7))) << 4);
                ldsm4(aAh + off, ah[mi]);
                ldsm4(aAl + off, al[mi]);
            }
            const int bk = ks * 16 + (lane & 15);
            #pragma unroll
            for (int p = 0; p < 4; p++){
                int u = wn * 8 + p * 2 + (lane >> 4);
                uint32_t off = bk * 256 + (((uint32_t)(u ^ (bk & 7))) << 4);
                ldsm4t(aBh + off, bb[2*p], bb[2*p+1]);
            }
            #pragma unroll
            for (int mi = 0; mi < 2; mi++)
                #pragma unroll
                for (int nj = 0; nj < 8; nj++)
                    mma16816(acc[mi][nj], ah[mi], bb[nj]);
            #pragma unroll
            for (int mi = 0; mi < 2; mi++)
                #pragma unroll
                for (int nj = 0; nj < 8; nj++)
                    mma16816(acc[mi][nj], al[mi], bb[nj]);
            #pragma unroll
            for (int p = 0; p < 4; p++){
                int u = wn * 8 + p * 2 + (lane >> 4);
                uint32_t off = bk * 256 + (((uint32_t)(u ^ (bk & 7))) << 4);
                ldsm4t(aBl + off, bb[2*p], bb[2*p+1]);
            }
            #pragma unroll
            for (int mi = 0; mi < 2; mi++)
                #pragma unroll
                for (int nj = 0; nj < 8; nj++)
                    mma16816(acc[mi][nj], ah[mi], bb[nj]);
        }

        if (kc + 2 < NK) fill(kc + 2, (kc + 2) % NSTAGES);
        else CP_COMMIT();
    }

    __syncthreads();
    float* sf = (float*)smem;
    {
        const int mrow = wm * 32 + (lane >> 2);
        const int ncol = wn * 64 + (lane & 3) * 2;
        #pragma unroll
        for (int mi = 0; mi < 2; mi++)
            #pragma unroll
            for (int nj = 0; nj < 8; nj++){
                int m = mrow + mi * 16, n = ncol + nj * 8;
                *(float2*)&sf[(size_t)m * 132 + n]       = make_float2(acc[mi][nj][0], acc[mi][nj][1]);
                *(float2*)&sf[(size_t)(m + 8) * 132 + n] = make_float2(acc[mi][nj][2], acc[mi][nj][3]);
            }
    }
    __syncthreads();

    for (int i = tid; i < BM * (BN / 4); i += 256){
        int r = i >> 5, c = (i & 31) * 4;
        float4 v = *(float4*)&sf[(size_t)r * 132 + c];
        float vv[4] = { v.x, v.y, v.z, v.w };
        #pragma unroll
        for (int j = 0; j < 4; j++)
            vv[j] += __ldg(biasN + col0 + c + j);
        *(float4*)(C + (size_t)(row0 + r) * N + col0 + c) = make_float4(vv[0], vv[1], vv[2], vv[3]);
    }
}

// ------------------------- SIDE GEMM 128x32 K-split (Bm|Cm partials) ----------
__global__ void __launch_bounds__(256, 1) k_tcS(
    const bf16* __restrict__ Ah, const bf16* __restrict__ Al,
    const bf16* __restrict__ Bh, const bf16* __restrict__ Bl,
    float* __restrict__ C, int K)
{
    extern __shared__ char smem[];
    const int tid = threadIdx.x;
    const int wid = tid >> 5, lane = tid & 31;
    const int row0 = blockIdx.y * 128;
    const int kc0 = blockIdx.x * (K / KSPLIT / 64);
    const int NK = K / KSPLIT / 64;
    const uint32_t sbase = smem_u32(smem);
    C += (size_t)blockIdx.x * ROWS * 32;

    float acc[4][4];
    #pragma unroll
    for (int nj = 0; nj < 4; nj++)
        #pragma unroll
        for (int q = 0; q < 4; q++) acc[nj][q] = 0.f;

    auto fill = [&](int kc, int s){
        uint32_t st = sbase + (uint32_t)s * SSTAGE;
        const bf16* ap[2] = { Ah, Al };
        #pragma unroll
        for (int arr = 0; arr < 2; arr++){
            uint32_t base = st + arr * SOFF_AL;
            #pragma unroll
            for (int it = 0; it < 4; it++){
                int id = tid + it * 256;
                int r = id >> 3, u = id & 7;
                cpa16(base + r * 128 + (((uint32_t)(u ^ (r & 7))) << 4),
                      ap[arr] + (size_t)(row0 + r) * K + (kc0 + kc) * 64 + u * 8);
            }
        }
        const bf16* bp[2] = { Bh, Bl };
        #pragma unroll
        for (int arr = 0; arr < 2; arr++){
            uint32_t base = st + SOFF_BH + arr * (SOFF_BL - SOFF_BH);
            int k = tid >> 2, u = tid & 3;
            cpa16(base + k * 64 + (((uint32_t)(u ^ (k & 3))) << 4),
                  bp[arr] + (size_t)((kc0 + kc) * 64 + k) * 32 + u * 8);
        }
        CP_COMMIT();
    };

    fill(0, 0);
    fill(1, 1);

    for (int kc = 0; kc < NK; kc++){
        int s = kc % 3;
        CP_WAIT(1);
        __syncthreads();

        uint32_t aAh = sbase + (uint32_t)s * SSTAGE;
        uint32_t aAl = aAh + SOFF_AL;
        uint32_t aBh = aAh + SOFF_BH;
        uint32_t aBl = aAh + SOFF_BL;

        #pragma unroll
        for (int ks = 0; ks < 4; ks++){
            uint32_t ah[4], al[4], bh[4][2], bl[4][2];
            const int r = wid * 16 + (lane & 15);
            const int au = 2 * ks + (lane >> 4);
            uint32_t offA = r * 128 + (((uint32_t)(au ^ (r & 7))) << 4);
            ldsm4(aAh + offA, ah);
            ldsm4(aAl + offA, al);
            const int bk = ks * 16 + (lane & 15);
            #pragma unroll
            for (int p = 0; p < 2; p++){
                int u = p * 2 + (lane >> 4);
                uint32_t off = bk * 64 + (((uint32_t)(u ^ (bk & 3))) << 4);
                ldsm4t(aBh + off, bh[2*p], bh[2*p+1]);
                ldsm4t(aBl + off, bl[2*p], bl[2*p+1]);
            }
            #pragma unroll
            for (int nj = 0; nj < 4; nj++){
                mma16816(acc[nj], ah, bh[nj]);
                mma16816(acc[nj], al, bh[nj]);
                mma16816(acc[nj], ah, bl[nj]);
            }
        }

        __syncthreads();
        if (kc + 2 < NK) fill(kc + 2, (kc + 2) % 3);
        else CP_COMMIT();
    }

    {
        int mrow = wid * 16 + (lane >> 2);
        int ncol = (lane & 3) * 2;
        #pragma unroll
        for (int nj = 0; nj < 4; nj++){
            int n = nj * 8 + ncol;
            *(float2*)&C[(size_t)(row0 + mrow) * 32 + n]     = make_float2(acc[nj][0], acc[nj][1]);
            *(float2*)&C[(size_t)(row0 + mrow + 8) * 32 + n] = make_float2(acc[nj][2], acc[nj][3]);
        }
    }
}

// ------------------------- prep: embed + all weight packs, one launch -------------------------
__device__ __forceinline__ void wsplit_job(int lb, int tid, const float* W,
                                           bf16* Wh, bf16* Wl, int Nsrc, int Ndst, int off)
{
    size_t i4 = (size_t)lb * 256 + tid;
    int nq = Nsrc / 4;
    int k  = (int)(i4 / nq);
    int c  = (int)(i4 % nq) * 4;
    float4 v = *(const float4*)(W + (size_t)k * Nsrc + c);
    bf16 hh[4], ll[4];
    splitf(v.x, hh[0], ll[0]); splitf(v.y, hh[1], ll[1]);
    splitf(v.z, hh[2], ll[2]); splitf(v.w, hh[3], ll[3]);
    size_t o = (size_t)k * Ndst + off + c;
    *(uint2*)(Wh + o) = *(uint2*)hh;
    *(uint2*)(Wl + o) = *(uint2*)ll;
}

__global__ void k_prep(const int* __restrict__ ids, const float* __restrict__ emb,
                       const float* __restrict__ W_in, const float* __restrict__ W_D,
                       const float* __restrict__ W_cl, const float* __restrict__ fc1_w,
                       const float* __restrict__ W_out,
                       const float* __restrict__ fc2_w, const float* __restrict__ fc3_w,
                       const float* __restrict__ conv_w,
                       const float* __restrict__ b_in, const float* __restrict__ b_D,
                       const float* __restrict__ fc2_b, const float* __restrict__ fc3_b)
{
    int bid = blockIdx.x;
    int tid = threadIdx.x;

    if (bid < ROWS){
        int row = bid;
        int id  = ids[row];
        const float* src = emb + (size_t)id * DMODEL;
        float s = 0.f, ss = 0.f;
        for (int d = tid; d < DMODEL; d += 256){
            float v = __ldg(src + d);
            g_x[(size_t)row * DMODEL + d] = v;
            s += v; ss += v * v;
        }
        __shared__ float sh[64];
        int lane = tid & 31, w = tid >> 5;
        #pragma unroll
        for (int o = 16; o; o >>= 1){
            s  += __shfl_down_sync(0xffffffffu, s,  o);
            ss += __shfl_down_sync(0xffffffffu, ss, o);
        }
        if (!lane){ sh[w] = s; sh[32 + w] = ss; }
        __syncthreads();
        if (tid == 0){
            float S = 0.f, SS = 0.f;
            for (int i = 0; i < 8; i++){ S += sh[i]; SS += sh[32 + i]; }
            g_rowsum[row] = S; g_rowsq[row] = SS;
        }
        return;
    }
    bid -= ROWS;
    if (bid < 1152){ wsplit_job(bid, tid, W_in, g_W15_h, g_W15_l, D2V, N2X, 0); return; }
    bid -= 1152;
    if (bid < 1152){ wsplit_job(bid, tid, W_D, g_W15_h, g_W15_l, D2V, N2X, D2V); return; }
    bid -= 1152;
    if (bid < 2304){ wsplit_job(bid, tid, W_cl, g_WclS_h, g_WclS_l, D2V, D2V, 0); return; }
    bid -= 2304;
    if (bid < 2304){ wsplit_job(bid, tid, fc1_w, g_f1_h, g_f1_l, D2V, D2V, 0); return; }
    bid -= 2304;
    if (bid < 1152){ wsplit_job(bid, tid, W_out, g_WoS_h, g_WoS_l, DMODEL, DMODEL, 0); return; }
    bid -= 1152;
    if (bid < 24){ wsplit_job(bid, tid, fc2_w, g_f23_h, g_f23_l, NSTATE, 32, 0); return; }
    bid -= 24;
    if (bid < 24){ wsplit_job(bid, tid, fc3_w, g_f23_h, g_f23_l, NSTATE, 32, NSTATE); return; }
    bid -= 24;
    if (bid < 4096){
        int o = bid >> 2;
        int i = (bid & 3) * 256 + tid;
        #pragma unroll
        for (int k = 0; k < 3; k++){
            float v = conv_w[(size_t)o * K3 + 3 * i + k];
            bf16 h, l; splitf(v, h, l);
            size_t off = (size_t)o * K3 + k * 1024 + i;
            g_cA_h[off] = h; g_cA_l[off] = l;
        }
        return;
    }
    bid -= 4096;
    if (bid < 12){
        int i = bid * 256 + tid;
        g_b15[i] = (i < D2V) ? b_in[i] : b_D[i - D2V];
        return;
    }
    bid -= 12;
    if (tid < 32) g_b23[tid] = (tid < NSTATE) ? fc2_b[tid] : fc3_b[tid - NSTATE];
}
#define PREP_BLOCKS (ROWS + 1152 + 1152 + 2304 + 2304 + 1152 + 24 + 24 + 4096 + 12 + 1)

// ------------------------- aux kernels -------------------------
__global__ void k_samplestats()
{
    int b = blockIdx.x;
    float s = 0.f, ss = 0.f;
    for (int r = threadIdx.x; r < LSEQ; r += blockDim.x){
        s += g_rowsum[b * LSEQ + r]; ss += g_rowsq[b * LSEQ + r];
    }
    __shared__ float sh[64];
    int lane = threadIdx.x & 31, w = threadIdx.x >> 5;
    #pragma unroll
    for (int o = 16; o; o >>= 1){
        s  += __shfl_down_sync(0xffffffffu, s,  o);
        ss += __shfl_down_sync(0xffffffffu, ss, o);
    }
    if (!lane){ sh[w] = s; sh[32 + w] = ss; }
    __syncthreads();
    if (threadIdx.x == 0){
        float S = 0.f, SS = 0.f;
        int nw = blockDim.x >> 5;
        for (int i = 0; i < nw; i++){ S += sh[i]; SS += sh[32 + i]; }
        float inv = 1.f / ((float)LSEQ * (float)DMODEL);
        float mu  = S * inv;
        float var = SS * inv - mu * mu;
        g_mu[b]   = mu;
        g_rsig[b] = rsqrtf(var + 1e-5f);
    }
}

__global__ void k_norm(const float* __restrict__ rms_w)
{
    int row = blockIdx.x;
    int b = row >> 10;
    float mu = g_mu[b], rs = g_rsig[b];
    float msq = rs * rs * (g_rowsq[row] - 2.f * mu * g_rowsum[row] + (float)DMODEL * mu * mu) / (float)DMODEL;
    float a = rs * rsqrtf(msq + 1e-5f);
    const float* xr = g_x + (size_t)row * DMODEL;
    for (int d = threadIdx.x; d < DMODEL; d += blockDim.x){
        float v = (xr[d] - mu) * a * rms_w[d];
        bf16 h, l; splitf(v, h, l);
        g_xnP_h[(size_t)row * DMODEL + d] = h;
        g_xnP_l[(size_t)row * DMODEL + d] = l;
    }
}

__global__ void k_convB()
{
    __shared__ float rowbuf[D2V + 2];
    int i = blockIdx.x, b = blockIdx.y;
    int t4 = threadIdx.x * 4;
    const float* src = g_xpr + ((size_t)(b * LSEQ) + i) * N2X;
    float4 v = *(const float4*)(src + t4);
    rowbuf[1 + t4 + 0] = v.x;
    rowbuf[1 + t4 + 1] = v.y;
    rowbuf[1 + t4 + 2] = v.z;
    rowbuf[1 + t4 + 3] = v.w;
    if (threadIdx.x == 0){ rowbuf[0] = 0.f; rowbuf[D2V + 1] = 0.f; }
    __syncthreads();
    #pragma unroll
    for (int k = 0; k < 3; k++){
        bf16 hh[4], ll[4];
        #pragma unroll
        for (int j = 0; j < 4; j++) splitf(rowbuf[t4 + k + j], hh[j], ll[j]);
        size_t o = (size_t)b * K3 * D2V + (size_t)(k * 1024 + i) * D2V + t4;
        *(uint2*)(g_cB_h + o) = *(uint2*)hh;
        *(uint2*)(g_cB_l + o) = *(uint2*)ll;
    }
}

__global__ void k_s()
{
    int row = blockIdx.x;
    int lane = threadIdx.x;
    float p = 0.f;
    if (lane < NSTATE){
        float bm = g_b23[lane], cm = g_b23[NSTATE + lane];
        #pragma unroll
        for (int ks = 0; ks < KSPLIT; ks++){
            bm += g_bc[((size_t)ks * ROWS + row) * 32 + lane];
            cm += g_bc[((size_t)ks * ROWS + row) * 32 + NSTATE + lane];
        }
        p = bm * cm;
    }
    #pragma unroll
    for (int o = 8; o; o >>= 1) p += __shfl_xor_sync(0xffffffffu, p, o);
    if (lane == 0) g_s[row] = p;
}

__global__ void k_maxpool(const float* __restrict__ out, float* __restrict__ pooled)
{
    int b = blockIdx.y;
    int d = blockIdx.x * blockDim.x + threadIdx.x;
    if (d >= DMODEL) return;
    const float* p = out + (size_t)b * LSEQ * DMODEL + d;
    float m = -FLT_MAX;
    for (int l = 0; l < LSEQ; l++) m = fmaxf(m, p[(size_t)l * DMODEL]);
    pooled[b * DMODEL + d] = m;
}

// ------------------------- launch -------------------------
extern "C" void kernel_launch(void* const* d_in, const int* in_sizes, int n_in,
                              void* d_out, int out_size)
{
    const int*   ids    = (const int*)  d_in[0];
    const float* emb    = (const float*)d_in[1];
    const float* rms_w  = (const float*)d_in[2];
    const float* W_in   = (const float*)d_in[3];
    const float* b_in   = (const float*)d_in[4];
    const float* conv_w = (const float*)d_in[5];
    const float* conv_b = (const float*)d_in[6];
    const float* W_cl   = (const float*)d_in[7];
    const float* b_cl   = (const float*)d_in[8];
    const float* fc1_w  = (const float*)d_in[9];
    const float* fc1_b  = (const float*)d_in[10];
    const float* fc2_w  = (const float*)d_in[11];
    const float* fc2_b  = (const float*)d_in[12];
    const float* fc3_w  = (const float*)d_in[13];
    const float* fc3_b  = (const float*)d_in[14];
    const float* W_D    = (const float*)d_in[16];
    const float* b_D    = (const float*)d_in[17];
    const float* W_out  = (const float*)d_in[18];
    const float* b_out  = (const float*)d_in[19];
    float* out = (float*)d_out;

    cudaFuncSetAttribute(k_tcW<0,false>, cudaFuncAttributeMaxDynamicSharedMemorySize, WSMEM);
    cudaFuncSetAttribute(k_tcW<0,true >, cudaFuncAttributeMaxDynamicSharedMemorySize, WSMEM);
    cudaFuncSetAttribute(k_tcW<1,true >, cudaFuncAttributeMaxDynamicSharedMemorySize, WSMEM);
    cudaFuncSetAttribute(k_tcW<5,true >, cudaFuncAttributeMaxDynamicSharedMemorySize, WSMEM);
    cudaFuncSetAttribute(k_tcN,          cudaFuncAttributeMaxDynamicSharedMemorySize, NSMEM);
    cudaFuncSetAttribute(k_tcS,          cudaFuncAttributeMaxDynamicSharedMemorySize, SSMEM);

    bf16 *xnh, *xnl, *xcah, *xcal, *xcoh, *xcol, *prh, *prl;
    bf16 *w15h, *w15l, *wclh, *wcll, *f1h, *f1l, *f23h, *f23l, *woh, *wol;
    bf16 *cah, *cal, *cbh, *cbl;
    float *pxpr, *pbc, *pb15, *ps;
    cudaGetSymbolAddress((void**)&xnh,  g_xnP_h);  cudaGetSymbolAddress((void**)&xnl,  g_xnP_l);
    cudaGetSymbolAddress((void**)&xcah, g_xcaP_h); cudaGetSymbolAddress((void**)&xcal, g_xcaP_l);
    cudaGetSymbolAddress((void**)&xcoh, g_xcoP_h); cudaGetSymbolAddress((void**)&xcol, g_xcoP_l);
    cudaGetSymbolAddress((void**)&prh,  g_prP_h);  cudaGetSymbolAddress((void**)&prl,  g_prP_l);
    cudaGetSymbolAddress((void**)&w15h, g_W15_h);  cudaGetSymbolAddress((void**)&w15l, g_W15_l);
    cudaGetSymbolAddress((void**)&wclh, g_WclS_h); cudaGetSymbolAddress((void**)&wcll, g_WclS_l);
    cudaGetSymbolAddress((void**)&f1h,  g_f1_h);   cudaGetSymbolAddress((void**)&f1l,  g_f1_l);
    cudaGetSymbolAddress((void**)&f23h, g_f23_h);  cudaGetSymbolAddress((void**)&f23l, g_f23_l);
    cudaGetSymbolAddress((void**)&woh,  g_WoS_h);  cudaGetSymbolAddress((void**)&wol,  g_WoS_l);
    cudaGetSymbolAddress((void**)&cah,  g_cA_h);   cudaGetSymbolAddress((void**)&cal,  g_cA_l);
    cudaGetSymbolAddress((void**)&cbh,  g_cB_h);   cudaGetSymbolAddress((void**)&cbl,  g_cB_l);
    cudaGetSymbolAddress((void**)&pxpr, g_xpr);
    cudaGetSymbolAddress((void**)&pbc,  g_bc);
    cudaGetSymbolAddress((void**)&pb15, g_b15);
    cudaGetSymbolAddress((void**)&ps,   g_s);

    // prep: embed + all weight/bias packs in one launch
    k_prep<<<PREP_BLOCKS, 256>>>(ids, emb, W_in, W_D, W_cl, fc1_w, W_out,
                                 fc2_w, fc3_w, conv_w, b_in, b_D, fc2_b, fc3_b);
    k_samplestats<<<BATCH, 256>>>();
    k_norm<<<ROWS, 256>>>(rms_w);

    // GEMM1+5: [xp | xres] = xn @ [W_in | W_D] + b  (fp32)
    k_tcW<0,false><<<dim3(N2X/256, ROWS/128, 1), 256, WSMEM>>>(
        xnh, xnl, w15h, w15l, pb15, nullptr, pxpr, nullptr, nullptr,
        nullptr, nullptr, nullptr, nullptr,
        DMODEL, N2X, 0, 0, 0);

    // conv operand gather
    k_convB<<<dim3(LSEQ, BATCH), 384>>>();

    // conv GEMM: xca = silu(cA @ cB + conv_b[row]), split out
    k_tcW<1,true><<<dim3(D2V/256, LSEQ/128, BATCH), 256, WSMEM>>>(
        cah, cal, cbh, cbl, nullptr, conv_b, nullptr, xcah, xcal,
        nullptr, nullptr, nullptr, nullptr,
        K3, D2V, 0, (long)K3*D2V, (long)LSEQ*D2V);

    // GEMM3: xco = xca @ W_cl + b_cl (split only)
    k_tcW<0,true><<<dim3(D2V/256, ROWS/128, 1), 256, WSMEM>>>(
        xcah, xcal, wclh, wcll, b_cl, nullptr, nullptr, xcoh, xcol,
        nullptr, nullptr, nullptr, nullptr,
        D2V, D2V, 0, 0, 0);

    // side GEMM (K-split 4): Bm/Cm partials
    k_tcS<<<dim3(KSPLIT, ROWS/128), 256, SSMEM>>>(xcoh, xcol, f23h, f23l, pbc, D2V);

    // s[row]
    k_s<<<ROWS, 32>>>();

    // GEMM4 (EPI5): prod split = silu(xco*softplus(xco@fc1+b1)*s) * silu(xres)
    k_tcW<5,true><<<dim3(D2V/256, ROWS/128, 1), 256, WSMEM>>>(
        xcoh, xcol, f1h, f1l, fc1_b, nullptr, nullptr, prh, prl,
        xcoh, xcol, pxpr, ps,
        D2V, D2V, 0, 0, 0);

    // GEMM6: out = prod @ W_out + b_out
    k_tcN<<<dim3(DMODEL/BN, ROWS/BM, 1), 256, NSMEM>>>(
        prh, prl, woh, wol, b_out, out, D2V, DMODEL);

    if (out_size >= ROWS * DMODEL + BATCH * DMODEL)
        k_maxpool<<<dim3((DMODEL + 255) / 256, BATCH), 256>>>(out, out + (size_t)ROWS * DMODEL);
}